// round 10
// baseline (speedup 1.0000x reference)
#include <cuda_runtime.h>
#include <cuda_fp16.h>
#include <stdint.h>

#define N_NODES   100000
#define N_EDGES   1200000
#define N_GRAPHS  128
#define D         64
#define N_CLASSES 10

#define SCAN_NB   ((N_NODES + 1023) / 1024)

// ---- device scratch (allocation-free) ----
__device__ __align__(128) unsigned g_hh [N_NODES * 32];  // GEMM out, half2-packed (128B/row)
__device__ __align__(128) unsigned g_hh2[N_NODES * 32];  // agg out (relu'd half), next GEMM input
__device__ __align__(128) float  g_dinv[N_NODES];
__device__ __align__(128) int    g_deg[N_NODES];
__device__ __align__(128) int    g_off[N_NODES + 1];
__device__ __align__(128) int    g_cursor[N_NODES];
__device__ __align__(128) float2 g_edge[N_EDGES];        // {src_as_bits, norm}
__device__ __align__(128) int    g_bsum[SCAN_NB];
__device__ __align__(128) float  g_pool[N_GRAPHS * D];
__device__ int g_lb[N_GRAPHS + 1];
__device__ int g_ei64;
__device__ int g_bat64;

// ---------------------------------------------------------------------------
// f32x2 packed FMA helpers (sm_103a)
// ---------------------------------------------------------------------------
__device__ __forceinline__ void fma2(unsigned long long& d,
                                     unsigned long long a,
                                     unsigned long long b) {
    asm("fma.rn.f32x2 %0, %1, %2, %0;" : "+l"(d) : "l"(a), "l"(b));
}
__device__ __forceinline__ unsigned long long dupf(float a) {
    unsigned long long u;
    asm("mov.b64 %0, {%1, %1};" : "=l"(u) : "f"(a));
    return u;
}
__device__ __forceinline__ float2 unpack2(unsigned long long u) {
    float2 f;
    asm("mov.b64 {%0, %1}, %2;" : "=f"(f.x), "=f"(f.y) : "l"(u));
    return f;
}
__device__ __forceinline__ void red_add_v4(float* addr, float4 v) {
    asm volatile("red.global.add.v4.f32 [%0], {%1, %2, %3, %4};"
                 :: "l"(addr), "f"(v.x), "f"(v.y), "f"(v.z), "f"(v.w)
                 : "memory");
}

// ---------------------------------------------------------------------------
// dtype detection + zero-init of pool
// ---------------------------------------------------------------------------
__global__ void detect_kernel(const int* ei_words, const int* bat_words) {
    int v = 0;
    for (int i = threadIdx.x; i < 2048; i += blockDim.x) v |= ei_words[2 * i + 1];
    int ei_nz = __syncthreads_or(v != 0);
    int w = 0;
    for (int i = threadIdx.x; i < 2048; i += blockDim.x) {
        int wi = N_NODES - 1 - 2 * i;
        wi -= (1 - (wi & 1));
        if (wi >= 1) w |= bat_words[wi];
    }
    int bat_nz = __syncthreads_or(w != 0);
    if (threadIdx.x == 0) { g_ei64 = ei_nz ? 0 : 1; g_bat64 = bat_nz ? 0 : 1; }
    for (int i = threadIdx.x; i < N_GRAPHS * D; i += blockDim.x) g_pool[i] = 0.f;
}

__device__ __forceinline__ int load_ei(const void* p, long long i) {
    return g_ei64 ? (int)((const long long*)p)[i] : ((const int*)p)[i];
}
__device__ __forceinline__ int load_bat(const void* p, int i) {
    return g_bat64 ? (int)((const long long*)p)[i] : ((const int*)p)[i];
}

// ---------------------------------------------------------------------------
// degree histogram + graph boundaries (merged; lb uses sorted batch)
// ---------------------------------------------------------------------------
__global__ void deglb_kernel(const void* __restrict__ ei,
                             const void* __restrict__ batch) {
    int e = blockIdx.x * blockDim.x + threadIdx.x;
    if (e < N_NODES) {
        int b0 = load_bat(batch, e);
        if (e == 0)
            for (int b = 0; b <= b0; b++) g_lb[b] = 0;
        int b1 = (e + 1 < N_NODES) ? load_bat(batch, e + 1) : N_GRAPHS;
        for (int b = b0 + 1; b <= b1; b++) g_lb[b] = e + 1;
    }
    if (e < N_EDGES)
        atomicAdd(&g_deg[load_ei(ei, (long long)N_EDGES + e)], 1);
}

// ---------------------------------------------------------------------------
// scan1: per-block (1024-item) sums of g_deg
// ---------------------------------------------------------------------------
__global__ void scan1_kernel() {
    __shared__ int s[256];
    int t = threadIdx.x;
    int base = blockIdx.x * 1024 + t * 4;
    int sum = 0;
    #pragma unroll
    for (int j = 0; j < 4; j++) { int i = base + j; if (i < N_NODES) sum += g_deg[i]; }
    s[t] = sum; __syncthreads();
    for (int o = 128; o > 0; o >>= 1) { if (t < o) s[t] += s[t + o]; __syncthreads(); }
    if (t == 0) g_bsum[blockIdx.x] = s[0];
}

// ---------------------------------------------------------------------------
// scan3: rescan block sums in smem, emit g_off/g_cursor + dinv (no atomics).
// ---------------------------------------------------------------------------
__global__ void scan3_kernel() {
    __shared__ int sb[128];
    __shared__ int ts[256];
    int t = threadIdx.x;

    if (t < 128) sb[t] = (t < SCAN_NB) ? g_bsum[t] : 0;
    __syncthreads();
    for (int o = 1; o < 128; o <<= 1) {
        int v = (t < 128 && t >= o) ? sb[t - o] : 0;
        __syncthreads();
        if (t < 128) sb[t] += v;
        __syncthreads();
    }
    int blockpre = (blockIdx.x == 0) ? 0 : sb[blockIdx.x - 1];

    int base = blockIdx.x * 1024 + t * 4;
    int v[4];
    #pragma unroll
    for (int j = 0; j < 4; j++) v[j] = (base + j < N_NODES) ? g_deg[base + j] : 0;
    ts[t] = v[0] + v[1] + v[2] + v[3]; __syncthreads();
    for (int o = 1; o < 256; o <<= 1) {
        int x = (t >= o) ? ts[t - o] : 0;
        __syncthreads(); ts[t] += x; __syncthreads();
    }
    int pre = blockpre + ((t == 0) ? 0 : ts[t - 1]);
    #pragma unroll
    for (int j = 0; j < 4; j++) {
        int i = base + j;
        if (i < N_NODES) {
            g_off[i] = pre; g_cursor[i] = pre;
            g_dinv[i] = rsqrtf((float)v[j] + 1.0f);
        }
        pre += v[j];
    }
    if (blockIdx.x == 0 && t == 0) g_off[N_NODES] = N_EDGES;
}

// CSR fill: payload = {src row bits, norm = dinv[r]*dinv[c]}
__global__ void fill_kernel(const void* __restrict__ ei) {
    int e = blockIdx.x * blockDim.x + threadIdx.x;
    if (e >= N_EDGES) return;
    int r = load_ei(ei, e);
    int c = load_ei(ei, (long long)N_EDGES + e);
    int pos = atomicAdd(&g_cursor[c], 1);
    g_edge[pos] = make_float2(__int_as_float(r), g_dinv[r] * g_dinv[c]);
}

// ---------------------------------------------------------------------------
// GEMM: g_hh(half) = A @ W.  A is fp32 (a_half=0, layer1 x) or relu'd fp16
// (a_half=1, g_hh2 from agg).  64-row tiles, 128 thr/block, f32x2 core.
// ---------------------------------------------------------------------------
#define SA_STRIDE 66
__global__ __launch_bounds__(128) void gemm_kernel(const void* __restrict__ A,
                                                   const float* __restrict__ W,
                                                   int a_half) {
    __shared__ float sA[64 * SA_STRIDE];
    __shared__ float sW[64 * 64];
    const int t = threadIdx.x;
    const int base = blockIdx.x * 64;

    for (int i = t; i < 1024; i += 128)
        ((float4*)sW)[i] = ((const float4*)W)[i];

    if (a_half) {
        // 64 rows x 8 uint4 (8 halves each)
        for (int i = t; i < 512; i += 128) {
            int row = i >> 3, s = i & 7;
            int gr = base + row;
            uint4 u = make_uint4(0u, 0u, 0u, 0u);
            if (gr < N_NODES) u = ((const uint4*)A)[gr * 8 + s];
            float* dst = sA + row * SA_STRIDE + s * 8;
            float2 f0 = __half22float2(*(half2*)&u.x);
            float2 f1 = __half22float2(*(half2*)&u.y);
            float2 f2 = __half22float2(*(half2*)&u.z);
            float2 f3 = __half22float2(*(half2*)&u.w);
            dst[0] = f0.x; dst[1] = f0.y; dst[2] = f1.x; dst[3] = f1.y;
            dst[4] = f2.x; dst[5] = f2.y; dst[6] = f3.x; dst[7] = f3.y;
        }
    } else {
        for (int i = t; i < 1024; i += 128) {
            int row = i >> 4, quad = i & 15;
            int gr = base + row;
            float4 v = make_float4(0.f, 0.f, 0.f, 0.f);
            if (gr < N_NODES) v = ((const float4*)A)[gr * 16 + quad];
            float* dst = sA + row * SA_STRIDE + quad * 4;
            dst[0] = v.x; dst[1] = v.y; dst[2] = v.z; dst[3] = v.w;
        }
    }
    __syncthreads();

    const int q2  = t & 7;
    const int grp = t >> 3;
    unsigned long long acc[4][4];
    #pragma unroll
    for (int r = 0; r < 4; r++)
        #pragma unroll
        for (int p = 0; p < 4; p++) acc[r][p] = 0ull;

    const float* wbase = sW + q2 * 8;
    const float* abase = sA + grp * 4 * SA_STRIDE;

    #pragma unroll 8
    for (int k = 0; k < 64; k++) {
        const float* wr = wbase + k * 64;
        unsigned long long w0 = *(const unsigned long long*)(wr + 0);
        unsigned long long w1 = *(const unsigned long long*)(wr + 2);
        unsigned long long w2 = *(const unsigned long long*)(wr + 4);
        unsigned long long w3 = *(const unsigned long long*)(wr + 6);
        #pragma unroll
        for (int r = 0; r < 4; r++) {
            unsigned long long a2 = dupf(abase[r * SA_STRIDE + k]);
            fma2(acc[r][0], a2, w0);
            fma2(acc[r][1], a2, w1);
            fma2(acc[r][2], a2, w2);
            fma2(acc[r][3], a2, w3);
        }
    }

    #pragma unroll
    for (int r = 0; r < 4; r++) {
        int gr = base + grp * 4 + r;
        if (gr >= N_NODES) continue;
        half2 h0 = __float22half2_rn(unpack2(acc[r][0]));
        half2 h1 = __float22half2_rn(unpack2(acc[r][1]));
        half2 h2 = __float22half2_rn(unpack2(acc[r][2]));
        half2 h3 = __float22half2_rn(unpack2(acc[r][3]));
        uint4 u;
        u.x = *(unsigned*)&h0; u.y = *(unsigned*)&h1;
        u.z = *(unsigned*)&h2; u.w = *(unsigned*)&h3;
        ((uint4*)g_hh)[gr * 8 + q2] = u;
    }
}

// ---------------------------------------------------------------------------
// CSR aggregation: 8 threads/node, LDG.128 fp16 gathers, unroll-4.
// mode 0: relu + half store to g_hh2 (feeds next GEMM).
// mode 1: fp32 red.v4 into g_pool (layer 3, no relu).
// ---------------------------------------------------------------------------
__device__ __forceinline__ void acc8h(float* a, uint4 u, float n) {
    float2 f0 = __half22float2(*(half2*)&u.x);
    float2 f1 = __half22float2(*(half2*)&u.y);
    float2 f2 = __half22float2(*(half2*)&u.z);
    float2 f3 = __half22float2(*(half2*)&u.w);
    a[0] += f0.x * n; a[1] += f0.y * n;
    a[2] += f1.x * n; a[3] += f1.y * n;
    a[4] += f2.x * n; a[5] += f2.y * n;
    a[6] += f3.x * n; a[7] += f3.y * n;
}

__global__ __launch_bounds__(256) void agg_kernel(const float* __restrict__ bias,
                                                  const void* __restrict__ batch,
                                                  int mode) {
    int gid = blockIdx.x * blockDim.x + threadIdx.x;
    if (gid >= N_NODES * 8) return;
    int node = gid >> 3, s = gid & 7;
    int j   = g_off[node];
    int end = g_off[node + 1];
    const uint4* h = (const uint4*)g_hh;    // 8 uint4 per row

    float a[8] = {0.f, 0.f, 0.f, 0.f, 0.f, 0.f, 0.f, 0.f};
    for (; j + 4 <= end; j += 4) {
        float2 e0 = g_edge[j],     e1 = g_edge[j + 1];
        float2 e2 = g_edge[j + 2], e3 = g_edge[j + 3];
        uint4 u0 = h[(__float_as_int(e0.x) << 3) + s];
        uint4 u1 = h[(__float_as_int(e1.x) << 3) + s];
        uint4 u2 = h[(__float_as_int(e2.x) << 3) + s];
        uint4 u3 = h[(__float_as_int(e3.x) << 3) + s];
        acc8h(a, u0, e0.y);
        acc8h(a, u1, e1.y);
        acc8h(a, u2, e2.y);
        acc8h(a, u3, e3.y);
    }
    for (; j < end; j++) {
        float2 e0 = g_edge[j];
        acc8h(a, h[(__float_as_int(e0.x) << 3) + s], e0.y);
    }
    // self loop + bias
    float di = g_dinv[node];
    acc8h(a, h[(node << 3) + s], di * di);
    const float4* b4 = (const float4*)(bias + s * 8);
    float4 bl = b4[0], bh = b4[1];
    a[0] += bl.x; a[1] += bl.y; a[2] += bl.z; a[3] += bl.w;
    a[4] += bh.x; a[5] += bh.y; a[6] += bh.z; a[7] += bh.w;

    if (mode) {
        int bg = load_bat(batch, node);
        float* dst = &g_pool[bg * D + s * 8];
        red_add_v4(dst,     make_float4(a[0], a[1], a[2], a[3]));
        red_add_v4(dst + 4, make_float4(a[4], a[5], a[6], a[7]));
    } else {
        // relu, then half
        #pragma unroll
        for (int i = 0; i < 8; i++) a[i] = fmaxf(a[i], 0.f);
        half2 h0 = __floats2half2_rn(a[0], a[1]);
        half2 h1 = __floats2half2_rn(a[2], a[3]);
        half2 h2 = __floats2half2_rn(a[4], a[5]);
        half2 h3 = __floats2half2_rn(a[6], a[7]);
        uint4 u;
        u.x = *(unsigned*)&h0; u.y = *(unsigned*)&h1;
        u.z = *(unsigned*)&h2; u.w = *(unsigned*)&h3;
        ((uint4*)g_hh2)[gid] = u;
    }
}

__global__ void final_kernel(const float* __restrict__ linW,
                             const float* __restrict__ linb,
                             float* __restrict__ out) {
    int id = blockIdx.x * blockDim.x + threadIdx.x;
    if (id >= N_GRAPHS * N_CLASSES) return;
    int b = id / N_CLASSES, c = id % N_CLASSES;
    int cnt = g_lb[b + 1] - g_lb[b];
    float inv = 1.0f / fmaxf((float)cnt, 1.0f);
    float acc = linb[c];
    #pragma unroll
    for (int d = 0; d < D; d++)
        acc += (g_pool[b * D + d] * inv) * linW[d * N_CLASSES + c];
    out[id] = acc;
}

extern "C" void kernel_launch(void* const* d_in, const int* in_sizes, int n_in,
                              void* d_out, int out_size) {
    const float* x    = (const float*)d_in[0];
    const void*  ei   = d_in[1];
    const void*  bat  = d_in[2];
    const float* W1   = (const float*)d_in[3];
    const float* b1   = (const float*)d_in[4];
    const float* W2   = (const float*)d_in[5];
    const float* b2   = (const float*)d_in[6];
    const float* W3   = (const float*)d_in[7];
    const float* b3   = (const float*)d_in[8];
    const float* linW = (const float*)d_in[9];
    const float* linb = (const float*)d_in[10];
    float* out = (float*)d_out;

    void *deg_p, *hh2_p;
    cudaGetSymbolAddress(&deg_p, g_deg);
    cudaGetSymbolAddress(&hh2_p, g_hh2);
    const void* hin = (const void*)hh2_p;

    cudaMemsetAsync(deg_p, 0, N_NODES * sizeof(int));

    const int GEMM_BLOCKS = (N_NODES + 63) / 64;
    const int NODE8       = (N_NODES * 8 + 255) / 256;

    detect_kernel<<<1, 256>>>((const int*)ei, (const int*)bat);
    deglb_kernel<<<(N_EDGES + 255) / 256, 256>>>(ei, bat);
    scan1_kernel<<<SCAN_NB, 256>>>();
    gemm_kernel<<<GEMM_BLOCKS, 128>>>(x, W1, 0);     // 5th launch -> profiled next round
    scan3_kernel<<<SCAN_NB, 256>>>();
    fill_kernel<<<(N_EDGES + 255) / 256, 256>>>(ei);

    agg_kernel<<<NODE8, 256>>>(b1, bat, 0);          // relu'd half -> g_hh2
    gemm_kernel<<<GEMM_BLOCKS, 128>>>(hin, W2, 1);
    agg_kernel<<<NODE8, 256>>>(b2, bat, 0);
    gemm_kernel<<<GEMM_BLOCKS, 128>>>(hin, W3, 1);
    agg_kernel<<<NODE8, 256>>>(b3, bat, 1);          // fused pool

    final_kernel<<<(N_GRAPHS * N_CLASSES + 255) / 256, 256>>>(linW, linb, out);
}

// round 11
// speedup vs baseline: 1.2467x; 1.2467x over previous
#include <cuda_runtime.h>
#include <cuda_fp16.h>
#include <stdint.h>

#define N_NODES   100000
#define N_EDGES   1200000
#define N_GRAPHS  128
#define D         64
#define N_CLASSES 10

#define SCAN_NB   ((N_NODES + 1023) / 1024)

// ---- device scratch (allocation-free) ----
__device__ __align__(128) unsigned g_hh [N_NODES * 32];  // GEMM out, half (128B/row)
__device__ __align__(128) unsigned g_hh2[N_NODES * 32];  // agg out (relu'd half), next GEMM in
__device__ __align__(128) float  g_dinv[N_NODES];
__device__ __align__(128) int    g_deg[N_NODES];
__device__ __align__(128) int    g_off[N_NODES + 1];
__device__ __align__(128) int    g_cursor[N_NODES];
__device__ __align__(128) float2 g_edge[N_EDGES];        // {src_as_bits, norm}
__device__ __align__(128) int    g_bsum[SCAN_NB];
__device__ __align__(128) float  g_pool[N_GRAPHS * D];
__device__ int g_lb[N_GRAPHS + 1];
__device__ int g_ei64;
__device__ int g_bat64;

__device__ __forceinline__ void red_add_v4(float* addr, float4 v) {
    asm volatile("red.global.add.v4.f32 [%0], {%1, %2, %3, %4};"
                 :: "l"(addr), "f"(v.x), "f"(v.y), "f"(v.z), "f"(v.w)
                 : "memory");
}

// m16n8k16 HMMA, f16 in / f32 accum
__device__ __forceinline__ void mma_16816(float* c,
                                          unsigned a0, unsigned a1,
                                          unsigned a2, unsigned a3,
                                          unsigned b0, unsigned b1) {
    asm volatile(
        "mma.sync.aligned.m16n8k16.row.col.f32.f16.f16.f32 "
        "{%0,%1,%2,%3}, {%4,%5,%6,%7}, {%8,%9}, {%0,%1,%2,%3};"
        : "+f"(c[0]), "+f"(c[1]), "+f"(c[2]), "+f"(c[3])
        : "r"(a0), "r"(a1), "r"(a2), "r"(a3), "r"(b0), "r"(b1));
}

// ---------------------------------------------------------------------------
// dtype detection + zero-init of pool
// ---------------------------------------------------------------------------
__global__ void detect_kernel(const int* ei_words, const int* bat_words) {
    int v = 0;
    for (int i = threadIdx.x; i < 2048; i += blockDim.x) v |= ei_words[2 * i + 1];
    int ei_nz = __syncthreads_or(v != 0);
    int w = 0;
    for (int i = threadIdx.x; i < 2048; i += blockDim.x) {
        int wi = N_NODES - 1 - 2 * i;
        wi -= (1 - (wi & 1));
        if (wi >= 1) w |= bat_words[wi];
    }
    int bat_nz = __syncthreads_or(w != 0);
    if (threadIdx.x == 0) { g_ei64 = ei_nz ? 0 : 1; g_bat64 = bat_nz ? 0 : 1; }
    for (int i = threadIdx.x; i < N_GRAPHS * D; i += blockDim.x) g_pool[i] = 0.f;
}

__device__ __forceinline__ int load_ei(const void* p, long long i) {
    return g_ei64 ? (int)((const long long*)p)[i] : ((const int*)p)[i];
}
__device__ __forceinline__ int load_bat(const void* p, int i) {
    return g_bat64 ? (int)((const long long*)p)[i] : ((const int*)p)[i];
}

// ---------------------------------------------------------------------------
// degree histogram + graph boundaries (merged)
// ---------------------------------------------------------------------------
__global__ void deglb_kernel(const void* __restrict__ ei,
                             const void* __restrict__ batch) {
    int e = blockIdx.x * blockDim.x + threadIdx.x;
    if (e < N_NODES) {
        int b0 = load_bat(batch, e);
        if (e == 0)
            for (int b = 0; b <= b0; b++) g_lb[b] = 0;
        int b1 = (e + 1 < N_NODES) ? load_bat(batch, e + 1) : N_GRAPHS;
        for (int b = b0 + 1; b <= b1; b++) g_lb[b] = e + 1;
    }
    if (e < N_EDGES)
        atomicAdd(&g_deg[load_ei(ei, (long long)N_EDGES + e)], 1);
}

// ---------------------------------------------------------------------------
// scan1: per-block (1024-item) sums of g_deg
// ---------------------------------------------------------------------------
__global__ void scan1_kernel() {
    __shared__ int s[256];
    int t = threadIdx.x;
    int base = blockIdx.x * 1024 + t * 4;
    int sum = 0;
    #pragma unroll
    for (int j = 0; j < 4; j++) { int i = base + j; if (i < N_NODES) sum += g_deg[i]; }
    s[t] = sum; __syncthreads();
    for (int o = 128; o > 0; o >>= 1) { if (t < o) s[t] += s[t + o]; __syncthreads(); }
    if (t == 0) g_bsum[blockIdx.x] = s[0];
}

// ---------------------------------------------------------------------------
// scan3: rescan block sums in smem, emit g_off/g_cursor + dinv
// ---------------------------------------------------------------------------
__global__ void scan3_kernel() {
    __shared__ int sb[128];
    __shared__ int ts[256];
    int t = threadIdx.x;

    if (t < 128) sb[t] = (t < SCAN_NB) ? g_bsum[t] : 0;
    __syncthreads();
    for (int o = 1; o < 128; o <<= 1) {
        int v = (t < 128 && t >= o) ? sb[t - o] : 0;
        __syncthreads();
        if (t < 128) sb[t] += v;
        __syncthreads();
    }
    int blockpre = (blockIdx.x == 0) ? 0 : sb[blockIdx.x - 1];

    int base = blockIdx.x * 1024 + t * 4;
    int v[4];
    #pragma unroll
    for (int j = 0; j < 4; j++) v[j] = (base + j < N_NODES) ? g_deg[base + j] : 0;
    ts[t] = v[0] + v[1] + v[2] + v[3]; __syncthreads();
    for (int o = 1; o < 256; o <<= 1) {
        int x = (t >= o) ? ts[t - o] : 0;
        __syncthreads(); ts[t] += x; __syncthreads();
    }
    int pre = blockpre + ((t == 0) ? 0 : ts[t - 1]);
    #pragma unroll
    for (int j = 0; j < 4; j++) {
        int i = base + j;
        if (i < N_NODES) {
            g_off[i] = pre; g_cursor[i] = pre;
            g_dinv[i] = rsqrtf((float)v[j] + 1.0f);
        }
        pre += v[j];
    }
    if (blockIdx.x == 0 && t == 0) g_off[N_NODES] = N_EDGES;
}

// CSR fill: payload = {src row bits, norm = dinv[r]*dinv[c]}
__global__ void fill_kernel(const void* __restrict__ ei) {
    int e = blockIdx.x * blockDim.x + threadIdx.x;
    if (e >= N_EDGES) return;
    int r = load_ei(ei, e);
    int c = load_ei(ei, (long long)N_EDGES + e);
    int pos = atomicAdd(&g_cursor[c], 1);
    g_edge[pos] = make_float2(__int_as_float(r), g_dinv[r] * g_dinv[c]);
}

// ---------------------------------------------------------------------------
// HMMA GEMM: g_hh(half) = A @ W.  A fp32 (a_half=0) or fp16 (a_half=1).
// 64 rows/block, 4 warps; warp w does rows w*16..+15 x all 64 cols.
// smem stride 72 halves (144B) -> conflict-free fragment loads (bank 4g+tg).
// ---------------------------------------------------------------------------
#define SH_STRIDE 72
__global__ __launch_bounds__(128) void gemm_kernel(const void* __restrict__ A,
                                                   const float* __restrict__ W,
                                                   int a_half) {
    __shared__ __align__(16) half sA[64 * SH_STRIDE];   // rows x k (reused as out)
    __shared__ __align__(16) half sB[64 * SH_STRIDE];   // n x k (transposed W)
    const int t = threadIdx.x;
    const int base = blockIdx.x * 64;

    // W [k][n] fp32 -> sB[n][k] fp16
    for (int i = t; i < 1024; i += 128) {
        int k = i >> 4, nq = i & 15;
        float4 w = ((const float4*)W)[i];
        sB[(nq * 4 + 0) * SH_STRIDE + k] = __float2half(w.x);
        sB[(nq * 4 + 1) * SH_STRIDE + k] = __float2half(w.y);
        sB[(nq * 4 + 2) * SH_STRIDE + k] = __float2half(w.z);
        sB[(nq * 4 + 3) * SH_STRIDE + k] = __float2half(w.w);
    }

    // A -> sA[row][k] fp16
    if (a_half) {
        for (int i = t; i < 512; i += 128) {
            int row = i >> 3, s = i & 7;
            int gr = base + row;
            uint4 u = make_uint4(0u, 0u, 0u, 0u);
            if (gr < N_NODES) u = ((const uint4*)A)[gr * 8 + s];
            *(uint4*)&sA[row * SH_STRIDE + s * 8] = u;
        }
    } else {
        for (int i = t; i < 1024; i += 128) {
            int row = i >> 4, q = i & 15;
            int gr = base + row;
            float4 v = make_float4(0.f, 0.f, 0.f, 0.f);
            if (gr < N_NODES) v = ((const float4*)A)[gr * 16 + q];
            half2 h01 = __floats2half2_rn(v.x, v.y);
            half2 h23 = __floats2half2_rn(v.z, v.w);
            uint2 u;
            u.x = *(unsigned*)&h01; u.y = *(unsigned*)&h23;
            *(uint2*)&sA[row * SH_STRIDE + q * 4] = u;
        }
    }
    __syncthreads();

    const int warp = t >> 5, lane = t & 31;
    const int g = lane >> 2, tg = lane & 3;
    const half* arow0 = sA + (warp * 16 + g) * SH_STRIDE;
    const half* arow8 = arow0 + 8 * SH_STRIDE;

    float c[8][4];
    #pragma unroll
    for (int nt = 0; nt < 8; nt++)
        #pragma unroll
        for (int p = 0; p < 4; p++) c[nt][p] = 0.f;

    #pragma unroll
    for (int kc = 0; kc < 4; kc++) {
        int k0 = kc * 16 + tg * 2;
        unsigned a0 = *(const unsigned*)(arow0 + k0);
        unsigned a1 = *(const unsigned*)(arow8 + k0);
        unsigned a2 = *(const unsigned*)(arow0 + k0 + 8);
        unsigned a3 = *(const unsigned*)(arow8 + k0 + 8);
        #pragma unroll
        for (int nt = 0; nt < 8; nt++) {
            const half* brow = sB + (nt * 8 + g) * SH_STRIDE + k0;
            unsigned b0 = *(const unsigned*)(brow);
            unsigned b1 = *(const unsigned*)(brow + 8);
            mma_16816(c[nt], a0, a1, a2, a3, b0, b1);
        }
    }

    // epilogue through smem (reuse sA) for coalesced stores
    __syncthreads();
    half* orow0 = sA + (warp * 16 + g) * SH_STRIDE;
    half* orow8 = orow0 + 8 * SH_STRIDE;
    #pragma unroll
    for (int nt = 0; nt < 8; nt++) {
        half2 h01 = __floats2half2_rn(c[nt][0], c[nt][1]);
        half2 h23 = __floats2half2_rn(c[nt][2], c[nt][3]);
        *(half2*)(orow0 + nt * 8 + tg * 2) = h01;
        *(half2*)(orow8 + nt * 8 + tg * 2) = h23;
    }
    __syncthreads();
    for (int i = t; i < 512; i += 128) {
        int row = i >> 3, s = i & 7;
        int gr = base + row;
        if (gr < N_NODES)
            ((uint4*)g_hh)[gr * 8 + s] = *(const uint4*)&sA[row * SH_STRIDE + s * 8];
    }
}

// ---------------------------------------------------------------------------
// CSR aggregation: 8 threads/node, LDG.128 fp16 gathers, unroll-4.
// mode 0: relu + half store to g_hh2.  mode 1: red.v4 into g_pool (layer 3).
// ---------------------------------------------------------------------------
__device__ __forceinline__ void acc8h(float* a, uint4 u, float n) {
    float2 f0 = __half22float2(*(half2*)&u.x);
    float2 f1 = __half22float2(*(half2*)&u.y);
    float2 f2 = __half22float2(*(half2*)&u.z);
    float2 f3 = __half22float2(*(half2*)&u.w);
    a[0] += f0.x * n; a[1] += f0.y * n;
    a[2] += f1.x * n; a[3] += f1.y * n;
    a[4] += f2.x * n; a[5] += f2.y * n;
    a[6] += f3.x * n; a[7] += f3.y * n;
}

__global__ __launch_bounds__(256) void agg_kernel(const float* __restrict__ bias,
                                                  const void* __restrict__ batch,
                                                  int mode) {
    int gid = blockIdx.x * blockDim.x + threadIdx.x;
    if (gid >= N_NODES * 8) return;
    int node = gid >> 3, s = gid & 7;
    int j   = g_off[node];
    int end = g_off[node + 1];
    const uint4* h = (const uint4*)g_hh;

    float a[8] = {0.f, 0.f, 0.f, 0.f, 0.f, 0.f, 0.f, 0.f};
    for (; j + 4 <= end; j += 4) {
        float2 e0 = g_edge[j],     e1 = g_edge[j + 1];
        float2 e2 = g_edge[j + 2], e3 = g_edge[j + 3];
        uint4 u0 = h[(__float_as_int(e0.x) << 3) + s];
        uint4 u1 = h[(__float_as_int(e1.x) << 3) + s];
        uint4 u2 = h[(__float_as_int(e2.x) << 3) + s];
        uint4 u3 = h[(__float_as_int(e3.x) << 3) + s];
        acc8h(a, u0, e0.y);
        acc8h(a, u1, e1.y);
        acc8h(a, u2, e2.y);
        acc8h(a, u3, e3.y);
    }
    for (; j < end; j++) {
        float2 e0 = g_edge[j];
        acc8h(a, h[(__float_as_int(e0.x) << 3) + s], e0.y);
    }
    float di = g_dinv[node];
    acc8h(a, h[(node << 3) + s], di * di);
    const float4* b4 = (const float4*)(bias + s * 8);
    float4 bl = b4[0], bh = b4[1];
    a[0] += bl.x; a[1] += bl.y; a[2] += bl.z; a[3] += bl.w;
    a[4] += bh.x; a[5] += bh.y; a[6] += bh.z; a[7] += bh.w;

    if (mode) {
        int bg = load_bat(batch, node);
        float* dst = &g_pool[bg * D + s * 8];
        red_add_v4(dst,     make_float4(a[0], a[1], a[2], a[3]));
        red_add_v4(dst + 4, make_float4(a[4], a[5], a[6], a[7]));
    } else {
        #pragma unroll
        for (int i = 0; i < 8; i++) a[i] = fmaxf(a[i], 0.f);
        half2 h0 = __floats2half2_rn(a[0], a[1]);
        half2 h1 = __floats2half2_rn(a[2], a[3]);
        half2 h2 = __floats2half2_rn(a[4], a[5]);
        half2 h3 = __floats2half2_rn(a[6], a[7]);
        uint4 u;
        u.x = *(unsigned*)&h0; u.y = *(unsigned*)&h1;
        u.z = *(unsigned*)&h2; u.w = *(unsigned*)&h3;
        ((uint4*)g_hh2)[gid] = u;
    }
}

__global__ void final_kernel(const float* __restrict__ linW,
                             const float* __restrict__ linb,
                             float* __restrict__ out) {
    int id = blockIdx.x * blockDim.x + threadIdx.x;
    if (id >= N_GRAPHS * N_CLASSES) return;
    int b = id / N_CLASSES, c = id % N_CLASSES;
    int cnt = g_lb[b + 1] - g_lb[b];
    float inv = 1.0f / fmaxf((float)cnt, 1.0f);
    float acc = linb[c];
    #pragma unroll
    for (int d = 0; d < D; d++)
        acc += (g_pool[b * D + d] * inv) * linW[d * N_CLASSES + c];
    out[id] = acc;
}

extern "C" void kernel_launch(void* const* d_in, const int* in_sizes, int n_in,
                              void* d_out, int out_size) {
    const float* x    = (const float*)d_in[0];
    const void*  ei   = d_in[1];
    const void*  bat  = d_in[2];
    const float* W1   = (const float*)d_in[3];
    const float* b1   = (const float*)d_in[4];
    const float* W2   = (const float*)d_in[5];
    const float* b2   = (const float*)d_in[6];
    const float* W3   = (const float*)d_in[7];
    const float* b3   = (const float*)d_in[8];
    const float* linW = (const float*)d_in[9];
    const float* linb = (const float*)d_in[10];
    float* out = (float*)d_out;

    void *deg_p, *hh2_p;
    cudaGetSymbolAddress(&deg_p, g_deg);
    cudaGetSymbolAddress(&hh2_p, g_hh2);
    const void* hin = (const void*)hh2_p;

    cudaMemsetAsync(deg_p, 0, N_NODES * sizeof(int));

    const int GEMM_BLOCKS = (N_NODES + 63) / 64;
    const int NODE8       = (N_NODES * 8 + 255) / 256;

    detect_kernel<<<1, 256>>>((const int*)ei, (const int*)bat);
    deglb_kernel<<<(N_EDGES + 255) / 256, 256>>>(ei, bat);
    scan1_kernel<<<SCAN_NB, 256>>>();
    gemm_kernel<<<GEMM_BLOCKS, 128>>>(x, W1, 0);     // 4th kernel -> profiled
    scan3_kernel<<<SCAN_NB, 256>>>();
    fill_kernel<<<(N_EDGES + 255) / 256, 256>>>(ei);

    agg_kernel<<<NODE8, 256>>>(b1, bat, 0);
    gemm_kernel<<<GEMM_BLOCKS, 128>>>(hin, W2, 1);
    agg_kernel<<<NODE8, 256>>>(b2, bat, 0);
    gemm_kernel<<<GEMM_BLOCKS, 128>>>(hin, W3, 1);
    agg_kernel<<<NODE8, 256>>>(b3, bat, 1);          // fused pool

    final_kernel<<<(N_GRAPHS * N_CLASSES + 255) / 256, 256>>>(linW, linb, out);
}

// round 12
// speedup vs baseline: 1.2650x; 1.0148x over previous
#include <cuda_runtime.h>
#include <cuda_fp16.h>
#include <stdint.h>

#define N_NODES   100000
#define N_EDGES   1200000
#define N_GRAPHS  128
#define D         64
#define N_CLASSES 10

#define SCAN_NB   ((N_NODES + 1023) / 1024)

// ---- device scratch (allocation-free) ----
__device__ __align__(128) unsigned g_hh [N_NODES * 32];  // GEMM out, half (128B/row)
__device__ __align__(128) unsigned g_hh2[N_NODES * 32];  // agg out (relu'd half)
__device__ __align__(128) unsigned g_wh[3 * 2048];       // W1..W3 as half2, n-major [n][k/2]
__device__ __align__(128) float  g_dinv[N_NODES];
__device__ __align__(128) int    g_deg[N_NODES];
__device__ __align__(128) int    g_off[N_NODES + 1];
__device__ __align__(128) int    g_cursor[N_NODES];
__device__ __align__(128) float2 g_edge[N_EDGES];        // {src_as_bits, norm}
__device__ __align__(128) int    g_bsum[SCAN_NB];
__device__ __align__(128) float  g_pool[N_GRAPHS * D];
__device__ int g_lb[N_GRAPHS + 1];
__device__ int g_ei64;
__device__ int g_bat64;

__device__ __forceinline__ void red_add_v4(float* addr, float4 v) {
    asm volatile("red.global.add.v4.f32 [%0], {%1, %2, %3, %4};"
                 :: "l"(addr), "f"(v.x), "f"(v.y), "f"(v.z), "f"(v.w)
                 : "memory");
}

// m16n8k16 HMMA, f16 in / f32 accum
__device__ __forceinline__ void mma_16816(float* c,
                                          unsigned a0, unsigned a1,
                                          unsigned a2, unsigned a3,
                                          unsigned b0, unsigned b1) {
    asm volatile(
        "mma.sync.aligned.m16n8k16.row.col.f32.f16.f16.f32 "
        "{%0,%1,%2,%3}, {%4,%5,%6,%7}, {%8,%9}, {%0,%1,%2,%3};"
        : "+f"(c[0]), "+f"(c[1]), "+f"(c[2]), "+f"(c[3])
        : "r"(a0), "r"(a1), "r"(a2), "r"(a3), "r"(b0), "r"(b1));
}

// ---------------------------------------------------------------------------
// detect dtypes + zero pool + convert W1..W3 to half (n-major) once
// ---------------------------------------------------------------------------
__global__ void detect_kernel(const int* ei_words, const int* bat_words,
                              const float* __restrict__ W1,
                              const float* __restrict__ W2,
                              const float* __restrict__ W3) {
    int v = 0;
    for (int i = threadIdx.x; i < 2048; i += blockDim.x) v |= ei_words[2 * i + 1];
    int ei_nz = __syncthreads_or(v != 0);
    int w = 0;
    for (int i = threadIdx.x; i < 2048; i += blockDim.x) {
        int wi = N_NODES - 1 - 2 * i;
        wi -= (1 - (wi & 1));
        if (wi >= 1) w |= bat_words[wi];
    }
    int bat_nz = __syncthreads_or(w != 0);
    if (threadIdx.x == 0) { g_ei64 = ei_nz ? 0 : 1; g_bat64 = bat_nz ? 0 : 1; }
    for (int i = threadIdx.x; i < N_GRAPHS * D; i += blockDim.x) g_pool[i] = 0.f;

    // W [k][n] fp32 -> g_wh [n][k/2] half2
    const float* Ws[3] = {W1, W2, W3};
    #pragma unroll
    for (int m = 0; m < 3; m++) {
        const float* W = Ws[m];
        for (int i = threadIdx.x; i < 2048; i += blockDim.x) {
            int n = i >> 5, kp = i & 31, k = kp * 2;
            half2 h = __floats2half2_rn(W[k * 64 + n], W[(k + 1) * 64 + n]);
            g_wh[m * 2048 + i] = *(unsigned*)&h;
        }
    }
}

__device__ __forceinline__ int load_ei(const void* p, long long i) {
    return g_ei64 ? (int)((const long long*)p)[i] : ((const int*)p)[i];
}
__device__ __forceinline__ int load_bat(const void* p, int i) {
    return g_bat64 ? (int)((const long long*)p)[i] : ((const int*)p)[i];
}

// ---------------------------------------------------------------------------
// degree histogram + graph boundaries (merged)
// ---------------------------------------------------------------------------
__global__ void deglb_kernel(const void* __restrict__ ei,
                             const void* __restrict__ batch) {
    int e = blockIdx.x * blockDim.x + threadIdx.x;
    if (e < N_NODES) {
        int b0 = load_bat(batch, e);
        if (e == 0)
            for (int b = 0; b <= b0; b++) g_lb[b] = 0;
        int b1 = (e + 1 < N_NODES) ? load_bat(batch, e + 1) : N_GRAPHS;
        for (int b = b0 + 1; b <= b1; b++) g_lb[b] = e + 1;
    }
    if (e < N_EDGES)
        atomicAdd(&g_deg[load_ei(ei, (long long)N_EDGES + e)], 1);
}

__global__ void scan1_kernel() {
    __shared__ int s[256];
    int t = threadIdx.x;
    int base = blockIdx.x * 1024 + t * 4;
    int sum = 0;
    #pragma unroll
    for (int j = 0; j < 4; j++) { int i = base + j; if (i < N_NODES) sum += g_deg[i]; }
    s[t] = sum; __syncthreads();
    for (int o = 128; o > 0; o >>= 1) { if (t < o) s[t] += s[t + o]; __syncthreads(); }
    if (t == 0) g_bsum[blockIdx.x] = s[0];
}

__global__ void scan3_kernel() {
    __shared__ int sb[128];
    __shared__ int ts[256];
    int t = threadIdx.x;

    if (t < 128) sb[t] = (t < SCAN_NB) ? g_bsum[t] : 0;
    __syncthreads();
    for (int o = 1; o < 128; o <<= 1) {
        int v = (t < 128 && t >= o) ? sb[t - o] : 0;
        __syncthreads();
        if (t < 128) sb[t] += v;
        __syncthreads();
    }
    int blockpre = (blockIdx.x == 0) ? 0 : sb[blockIdx.x - 1];

    int base = blockIdx.x * 1024 + t * 4;
    int v[4];
    #pragma unroll
    for (int j = 0; j < 4; j++) v[j] = (base + j < N_NODES) ? g_deg[base + j] : 0;
    ts[t] = v[0] + v[1] + v[2] + v[3]; __syncthreads();
    for (int o = 1; o < 256; o <<= 1) {
        int x = (t >= o) ? ts[t - o] : 0;
        __syncthreads(); ts[t] += x; __syncthreads();
    }
    int pre = blockpre + ((t == 0) ? 0 : ts[t - 1]);
    #pragma unroll
    for (int j = 0; j < 4; j++) {
        int i = base + j;
        if (i < N_NODES) {
            g_off[i] = pre; g_cursor[i] = pre;
            g_dinv[i] = rsqrtf((float)v[j] + 1.0f);
        }
        pre += v[j];
    }
    if (blockIdx.x == 0 && t == 0) g_off[N_NODES] = N_EDGES;
}

__global__ void fill_kernel(const void* __restrict__ ei) {
    int e = blockIdx.x * blockDim.x + threadIdx.x;
    if (e >= N_EDGES) return;
    int r = load_ei(ei, e);
    int c = load_ei(ei, (long long)N_EDGES + e);
    int pos = atomicAdd(&g_cursor[c], 1);
    g_edge[pos] = make_float2(__int_as_float(r), g_dinv[r] * g_dinv[c]);
}

// ---------------------------------------------------------------------------
// HMMA GEMM: g_hh(half) = A @ W.  256 rows/block, 8 warps.
// Warp w: rows w*32..+31 (2 m16 tiles) x 64 cols (8 n8 tiles), K=64 (4 chunks).
// W preconverted to half n-major (wh).  smem stride 72 halves, conflict-free.
// ---------------------------------------------------------------------------
#define SH_STRIDE 72
#define GEMM_ROWS 256
__global__ __launch_bounds__(256) void gemm_kernel(const void* __restrict__ A,
                                                   const unsigned* __restrict__ wh,
                                                   int a_half) {
    __shared__ __align__(16) half sA[GEMM_ROWS * SH_STRIDE];   // 36.9KB (reused as out)
    __shared__ __align__(16) half sB[64 * SH_STRIDE];          // 9.2KB
    const int t = threadIdx.x;
    const int base = blockIdx.x * GEMM_ROWS;

    // W half [n][k] -> sB rows (8 uint4 per n-row)
    for (int i = t; i < 512; i += 256) {
        int n = i >> 3, s = i & 7;
        *(uint4*)&sB[n * SH_STRIDE + s * 8] = ((const uint4*)wh)[i];
    }

    // A -> sA[row][k] fp16
    if (a_half) {
        for (int i = t; i < GEMM_ROWS * 8; i += 256) {
            int row = i >> 3, s = i & 7;
            int gr = base + row;
            uint4 u = make_uint4(0u, 0u, 0u, 0u);
            if (gr < N_NODES) u = ((const uint4*)A)[gr * 8 + s];
            *(uint4*)&sA[row * SH_STRIDE + s * 8] = u;
        }
    } else {
        for (int i = t; i < GEMM_ROWS * 16; i += 256) {
            int row = i >> 4, q = i & 15;
            int gr = base + row;
            float4 v = make_float4(0.f, 0.f, 0.f, 0.f);
            if (gr < N_NODES) v = ((const float4*)A)[gr * 16 + q];
            half2 h01 = __floats2half2_rn(v.x, v.y);
            half2 h23 = __floats2half2_rn(v.z, v.w);
            uint2 u;
            u.x = *(unsigned*)&h01; u.y = *(unsigned*)&h23;
            *(uint2*)&sA[row * SH_STRIDE + q * 4] = u;
        }
    }
    __syncthreads();

    const int warp = t >> 5, lane = t & 31;
    const int g = lane >> 2, tg = lane & 3;

    float c[2][8][4];
    #pragma unroll
    for (int rt = 0; rt < 2; rt++)
        #pragma unroll
        for (int nt = 0; nt < 8; nt++)
            #pragma unroll
            for (int p = 0; p < 4; p++) c[rt][nt][p] = 0.f;

    #pragma unroll
    for (int kc = 0; kc < 4; kc++) {
        int k0 = kc * 16 + tg * 2;
        unsigned a[2][4];
        #pragma unroll
        for (int rt = 0; rt < 2; rt++) {
            const half* r0 = sA + (warp * 32 + rt * 16 + g) * SH_STRIDE;
            const half* r8 = r0 + 8 * SH_STRIDE;
            a[rt][0] = *(const unsigned*)(r0 + k0);
            a[rt][1] = *(const unsigned*)(r8 + k0);
            a[rt][2] = *(const unsigned*)(r0 + k0 + 8);
            a[rt][3] = *(const unsigned*)(r8 + k0 + 8);
        }
        #pragma unroll
        for (int nt = 0; nt < 8; nt++) {
            const half* brow = sB + (nt * 8 + g) * SH_STRIDE + k0;
            unsigned b0 = *(const unsigned*)(brow);
            unsigned b1 = *(const unsigned*)(brow + 8);
            mma_16816(c[0][nt], a[0][0], a[0][1], a[0][2], a[0][3], b0, b1);
            mma_16816(c[1][nt], a[1][0], a[1][1], a[1][2], a[1][3], b0, b1);
        }
    }

    // epilogue through smem (reuse sA)
    __syncthreads();
    #pragma unroll
    for (int rt = 0; rt < 2; rt++) {
        half* o0 = sA + (warp * 32 + rt * 16 + g) * SH_STRIDE;
        half* o8 = o0 + 8 * SH_STRIDE;
        #pragma unroll
        for (int nt = 0; nt < 8; nt++) {
            half2 h01 = __floats2half2_rn(c[rt][nt][0], c[rt][nt][1]);
            half2 h23 = __floats2half2_rn(c[rt][nt][2], c[rt][nt][3]);
            *(half2*)(o0 + nt * 8 + tg * 2) = h01;
            *(half2*)(o8 + nt * 8 + tg * 2) = h23;
        }
    }
    __syncthreads();
    for (int i = t; i < GEMM_ROWS * 8; i += 256) {
        int row = i >> 3, s = i & 7;
        int gr = base + row;
        if (gr < N_NODES)
            ((uint4*)g_hh)[gr * 8 + s] = *(const uint4*)&sA[row * SH_STRIDE + s * 8];
    }
}

// ---------------------------------------------------------------------------
// CSR aggregation: 8 threads/node, LDG.128 fp16 gathers, unroll-4.
// mode 0: relu + half store to g_hh2.  mode 1: red.v4 into g_pool (layer 3).
// ---------------------------------------------------------------------------
__device__ __forceinline__ void acc8h(float* a, uint4 u, float n) {
    float2 f0 = __half22float2(*(half2*)&u.x);
    float2 f1 = __half22float2(*(half2*)&u.y);
    float2 f2 = __half22float2(*(half2*)&u.z);
    float2 f3 = __half22float2(*(half2*)&u.w);
    a[0] += f0.x * n; a[1] += f0.y * n;
    a[2] += f1.x * n; a[3] += f1.y * n;
    a[4] += f2.x * n; a[5] += f2.y * n;
    a[6] += f3.x * n; a[7] += f3.y * n;
}

__global__ __launch_bounds__(256) void agg_kernel(const float* __restrict__ bias,
                                                  const void* __restrict__ batch,
                                                  int mode) {
    int gid = blockIdx.x * blockDim.x + threadIdx.x;
    if (gid >= N_NODES * 8) return;
    int node = gid >> 3, s = gid & 7;
    int j   = g_off[node];
    int end = g_off[node + 1];
    const uint4* h = (const uint4*)g_hh;

    float a[8] = {0.f, 0.f, 0.f, 0.f, 0.f, 0.f, 0.f, 0.f};
    for (; j + 4 <= end; j += 4) {
        float2 e0 = g_edge[j],     e1 = g_edge[j + 1];
        float2 e2 = g_edge[j + 2], e3 = g_edge[j + 3];
        uint4 u0 = h[(__float_as_int(e0.x) << 3) + s];
        uint4 u1 = h[(__float_as_int(e1.x) << 3) + s];
        uint4 u2 = h[(__float_as_int(e2.x) << 3) + s];
        uint4 u3 = h[(__float_as_int(e3.x) << 3) + s];
        acc8h(a, u0, e0.y);
        acc8h(a, u1, e1.y);
        acc8h(a, u2, e2.y);
        acc8h(a, u3, e3.y);
    }
    for (; j < end; j++) {
        float2 e0 = g_edge[j];
        acc8h(a, h[(__float_as_int(e0.x) << 3) + s], e0.y);
    }
    float di = g_dinv[node];
    acc8h(a, h[(node << 3) + s], di * di);
    const float4* b4 = (const float4*)(bias + s * 8);
    float4 bl = b4[0], bh = b4[1];
    a[0] += bl.x; a[1] += bl.y; a[2] += bl.z; a[3] += bl.w;
    a[4] += bh.x; a[5] += bh.y; a[6] += bh.z; a[7] += bh.w;

    if (mode) {
        int bg = load_bat(batch, node);
        float* dst = &g_pool[bg * D + s * 8];
        red_add_v4(dst,     make_float4(a[0], a[1], a[2], a[3]));
        red_add_v4(dst + 4, make_float4(a[4], a[5], a[6], a[7]));
    } else {
        #pragma unroll
        for (int i = 0; i < 8; i++) a[i] = fmaxf(a[i], 0.f);
        half2 h0 = __floats2half2_rn(a[0], a[1]);
        half2 h1 = __floats2half2_rn(a[2], a[3]);
        half2 h2 = __floats2half2_rn(a[4], a[5]);
        half2 h3 = __floats2half2_rn(a[6], a[7]);
        uint4 u;
        u.x = *(unsigned*)&h0; u.y = *(unsigned*)&h1;
        u.z = *(unsigned*)&h2; u.w = *(unsigned*)&h3;
        ((uint4*)g_hh2)[gid] = u;
    }
}

__global__ void final_kernel(const float* __restrict__ linW,
                             const float* __restrict__ linb,
                             float* __restrict__ out) {
    int id = blockIdx.x * blockDim.x + threadIdx.x;
    if (id >= N_GRAPHS * N_CLASSES) return;
    int b = id / N_CLASSES, c = id % N_CLASSES;
    int cnt = g_lb[b + 1] - g_lb[b];
    float inv = 1.0f / fmaxf((float)cnt, 1.0f);
    float acc = linb[c];
    #pragma unroll
    for (int d = 0; d < D; d++)
        acc += (g_pool[b * D + d] * inv) * linW[d * N_CLASSES + c];
    out[id] = acc;
}

extern "C" void kernel_launch(void* const* d_in, const int* in_sizes, int n_in,
                              void* d_out, int out_size) {
    const float* x    = (const float*)d_in[0];
    const void*  ei   = d_in[1];
    const void*  bat  = d_in[2];
    const float* W1   = (const float*)d_in[3];
    const float* b1   = (const float*)d_in[4];
    const float* W2   = (const float*)d_in[5];
    const float* b2   = (const float*)d_in[6];
    const float* W3   = (const float*)d_in[7];
    const float* b3   = (const float*)d_in[8];
    const float* linW = (const float*)d_in[9];
    const float* linb = (const float*)d_in[10];
    float* out = (float*)d_out;

    void *deg_p, *hh2_p, *wh_p;
    cudaGetSymbolAddress(&deg_p, g_deg);
    cudaGetSymbolAddress(&hh2_p, g_hh2);
    cudaGetSymbolAddress(&wh_p,  g_wh);
    const void* hin = (const void*)hh2_p;
    const unsigned* wh = (const unsigned*)wh_p;

    cudaMemsetAsync(deg_p, 0, N_NODES * sizeof(int));

    const int GEMM_BLOCKS = (N_NODES + GEMM_ROWS - 1) / GEMM_ROWS;
    const int NODE8       = (N_NODES * 8 + 255) / 256;

    detect_kernel<<<1, 256>>>((const int*)ei, (const int*)bat, W1, W2, W3);
    deglb_kernel<<<(N_EDGES + 255) / 256, 256>>>(ei, bat);
    scan1_kernel<<<SCAN_NB, 256>>>();
    gemm_kernel<<<GEMM_BLOCKS, 256>>>(x, wh + 0 * 2048, 0);   // 4th -> profiled
    scan3_kernel<<<SCAN_NB, 256>>>();
    fill_kernel<<<(N_EDGES + 255) / 256, 256>>>(ei);

    agg_kernel<<<NODE8, 256>>>(b1, bat, 0);
    gemm_kernel<<<GEMM_BLOCKS, 256>>>(hin, wh + 1 * 2048, 1);
    agg_kernel<<<NODE8, 256>>>(b2, bat, 0);
    gemm_kernel<<<GEMM_BLOCKS, 256>>>(hin, wh + 2 * 2048, 1);
    agg_kernel<<<NODE8, 256>>>(b3, bat, 1);          // fused pool

    final_kernel<<<(N_GRAPHS * N_CLASSES + 255) / 256, 256>>>(linW, linb, out);
}

// round 13
// speedup vs baseline: 1.3068x; 1.0330x over previous
#include <cuda_runtime.h>
#include <cuda_fp16.h>
#include <stdint.h>

#define N_NODES   100000
#define N_EDGES   1200000
#define N_GRAPHS  128
#define D         64
#define N_CLASSES 10

#define SCAN_NB   ((N_NODES + 1023) / 1024)

#define GR        128                     // gemm tile rows
#define TILES     ((N_NODES + GR - 1) / GR)   // 782
#define PAD_ROWS  (TILES * GR)                // 100096

// ---- device scratch (allocation-free) ----
__device__ __align__(128) unsigned g_hh [PAD_ROWS * 32];  // half feature buf A (128B/row)
__device__ __align__(128) unsigned g_hh2[PAD_ROWS * 32];  // half feature buf B
__device__ __align__(128) unsigned g_wh[3 * 2048];        // W1..W3 half2, n-major [n][k/2]
__device__ __align__(128) float  g_dinv[N_NODES];
__device__ __align__(128) int    g_deg[N_NODES];
__device__ __align__(128) int    g_off[N_NODES + 1];
__device__ __align__(128) int    g_cursor[N_NODES];
__device__ __align__(128) float2 g_edge[N_EDGES];         // {src_as_bits, norm}
__device__ __align__(128) int    g_bsum[SCAN_NB];
__device__ __align__(128) float  g_pool[N_GRAPHS * D];
__device__ int g_lb[N_GRAPHS + 1];
__device__ int g_ei64;
__device__ int g_bat64;

__device__ __forceinline__ void red_add_v4(float* addr, float4 v) {
    asm volatile("red.global.add.v4.f32 [%0], {%1, %2, %3, %4};"
                 :: "l"(addr), "f"(v.x), "f"(v.y), "f"(v.z), "f"(v.w)
                 : "memory");
}

// m16n8k16 HMMA, f16 in / f32 accum
__device__ __forceinline__ void mma_16816(float* c,
                                          unsigned a0, unsigned a1,
                                          unsigned a2, unsigned a3,
                                          unsigned b0, unsigned b1) {
    asm volatile(
        "mma.sync.aligned.m16n8k16.row.col.f32.f16.f16.f32 "
        "{%0,%1,%2,%3}, {%4,%5,%6,%7}, {%8,%9}, {%0,%1,%2,%3};"
        : "+f"(c[0]), "+f"(c[1]), "+f"(c[2]), "+f"(c[3])
        : "r"(a0), "r"(a1), "r"(a2), "r"(a3), "r"(b0), "r"(b1));
}

__device__ __forceinline__ void cp16(unsigned dst_smem, const void* src) {
    asm volatile("cp.async.cg.shared.global [%0], [%1], 16;"
                 :: "r"(dst_smem), "l"(src));
}

// ---------------------------------------------------------------------------
// detect dtypes + zero pool + convert W1..W3 to half (n-major) once
// ---------------------------------------------------------------------------
__global__ void detect_kernel(const int* ei_words, const int* bat_words,
                              const float* __restrict__ W1,
                              const float* __restrict__ W2,
                              const float* __restrict__ W3) {
    int v = 0;
    for (int i = threadIdx.x; i < 2048; i += blockDim.x) v |= ei_words[2 * i + 1];
    int ei_nz = __syncthreads_or(v != 0);
    int w = 0;
    for (int i = threadIdx.x; i < 2048; i += blockDim.x) {
        int wi = N_NODES - 1 - 2 * i;
        wi -= (1 - (wi & 1));
        if (wi >= 1) w |= bat_words[wi];
    }
    int bat_nz = __syncthreads_or(w != 0);
    if (threadIdx.x == 0) { g_ei64 = ei_nz ? 0 : 1; g_bat64 = bat_nz ? 0 : 1; }
    for (int i = threadIdx.x; i < N_GRAPHS * D; i += blockDim.x) g_pool[i] = 0.f;

    const float* Ws[3] = {W1, W2, W3};
    #pragma unroll
    for (int m = 0; m < 3; m++) {
        const float* W = Ws[m];
        for (int i = threadIdx.x; i < 2048; i += blockDim.x) {
            int n = i >> 5, kp = i & 31, k = kp * 2;
            half2 h = __floats2half2_rn(W[k * 64 + n], W[(k + 1) * 64 + n]);
            g_wh[m * 2048 + i] = *(unsigned*)&h;
        }
    }
}

__device__ __forceinline__ int load_ei(const void* p, long long i) {
    return g_ei64 ? (int)((const long long*)p)[i] : ((const int*)p)[i];
}
__device__ __forceinline__ int load_bat(const void* p, int i) {
    return g_bat64 ? (int)((const long long*)p)[i] : ((const int*)p)[i];
}

// ---------------------------------------------------------------------------
// deglb: degree atomics + graph boundaries + x fp32 -> half (padded rows)
// ---------------------------------------------------------------------------
__global__ void deglb_kernel(const void* __restrict__ ei,
                             const void* __restrict__ batch,
                             const float* __restrict__ x,
                             uint4* __restrict__ xh) {
    int e = blockIdx.x * blockDim.x + threadIdx.x;
    if (e < N_NODES) {
        int b0 = load_bat(batch, e);
        if (e == 0)
            for (int b = 0; b <= b0; b++) g_lb[b] = 0;
        int b1 = (e + 1 < N_NODES) ? load_bat(batch, e + 1) : N_GRAPHS;
        for (int b = b0 + 1; b <= b1; b++) g_lb[b] = e + 1;
    }
    if (e < PAD_ROWS * 8) {
        int gr = e >> 3, s = e & 7;
        uint4 u = make_uint4(0u, 0u, 0u, 0u);
        if (gr < N_NODES) {
            float4 v0 = ((const float4*)x)[gr * 16 + s * 2];
            float4 v1 = ((const float4*)x)[gr * 16 + s * 2 + 1];
            half2 h0 = __floats2half2_rn(v0.x, v0.y);
            half2 h1 = __floats2half2_rn(v0.z, v0.w);
            half2 h2 = __floats2half2_rn(v1.x, v1.y);
            half2 h3 = __floats2half2_rn(v1.z, v1.w);
            u.x = *(unsigned*)&h0; u.y = *(unsigned*)&h1;
            u.z = *(unsigned*)&h2; u.w = *(unsigned*)&h3;
        }
        xh[gr * 8 + s] = u;
    }
    if (e < N_EDGES)
        atomicAdd(&g_deg[load_ei(ei, (long long)N_EDGES + e)], 1);
}

__global__ void scan1_kernel() {
    __shared__ int s[256];
    int t = threadIdx.x;
    int base = blockIdx.x * 1024 + t * 4;
    int sum = 0;
    #pragma unroll
    for (int j = 0; j < 4; j++) { int i = base + j; if (i < N_NODES) sum += g_deg[i]; }
    s[t] = sum; __syncthreads();
    for (int o = 128; o > 0; o >>= 1) { if (t < o) s[t] += s[t + o]; __syncthreads(); }
    if (t == 0) g_bsum[blockIdx.x] = s[0];
}

__global__ void scan3_kernel() {
    __shared__ int sb[128];
    __shared__ int ts[256];
    int t = threadIdx.x;

    if (t < 128) sb[t] = (t < SCAN_NB) ? g_bsum[t] : 0;
    __syncthreads();
    for (int o = 1; o < 128; o <<= 1) {
        int v = (t < 128 && t >= o) ? sb[t - o] : 0;
        __syncthreads();
        if (t < 128) sb[t] += v;
        __syncthreads();
    }
    int blockpre = (blockIdx.x == 0) ? 0 : sb[blockIdx.x - 1];

    int base = blockIdx.x * 1024 + t * 4;
    int v[4];
    #pragma unroll
    for (int j = 0; j < 4; j++) v[j] = (base + j < N_NODES) ? g_deg[base + j] : 0;
    ts[t] = v[0] + v[1] + v[2] + v[3]; __syncthreads();
    for (int o = 1; o < 256; o <<= 1) {
        int x = (t >= o) ? ts[t - o] : 0;
        __syncthreads(); ts[t] += x; __syncthreads();
    }
    int pre = blockpre + ((t == 0) ? 0 : ts[t - 1]);
    #pragma unroll
    for (int j = 0; j < 4; j++) {
        int i = base + j;
        if (i < N_NODES) {
            g_off[i] = pre; g_cursor[i] = pre;
            g_dinv[i] = rsqrtf((float)v[j] + 1.0f);
        }
        pre += v[j];
    }
    if (blockIdx.x == 0 && t == 0) g_off[N_NODES] = N_EDGES;
}

__global__ void fill_kernel(const void* __restrict__ ei) {
    int e = blockIdx.x * blockDim.x + threadIdx.x;
    if (e >= N_EDGES) return;
    int r = load_ei(ei, e);
    int c = load_ei(ei, (long long)N_EDGES + e);
    int pos = atomicAdd(&g_cursor[c], 1);
    g_edge[pos] = make_float2(__int_as_float(r), g_dinv[r] * g_dinv[c]);
}

// ---------------------------------------------------------------------------
// Persistent double-buffered HMMA GEMM: Aout(half) = Ain(half,padded) @ W.
// 391 blocks x 2 tiles of 128 rows; cp.async prefetch overlaps MMA.
// 8 warps: warp w -> rows w*16..+15 x 64 cols. smem stride 72, conflict-free.
// ---------------------------------------------------------------------------
#define SH_STRIDE 72
__global__ __launch_bounds__(256) void gemm_kernel(const uint4* __restrict__ Ain,
                                                   half* __restrict__ Aout,
                                                   const unsigned* __restrict__ wh) {
    __shared__ __align__(16) half sA[2][GR * SH_STRIDE];   // 2 x 18.4KB
    __shared__ __align__(16) half sB[64 * SH_STRIDE];      // 9.2KB
    const int t = threadIdx.x;

    for (int i = t; i < 512; i += 256) {
        int n = i >> 3, s = i & 7;
        *(uint4*)&sB[n * SH_STRIDE + s * 8] = ((const uint4*)wh)[i];
    }

    const int warp = t >> 5, lane = t & 31;
    const int g = lane >> 2, tg = lane & 3;

    // prologue prefetch: tile = blockIdx.x into buf 0
    {
        unsigned sbase = (unsigned)__cvta_generic_to_shared(&sA[0][0]);
        #pragma unroll
        for (int j = 0; j < 4; j++) {
            int i = t + 256 * j;
            int row = i >> 3, s = i & 7;
            cp16(sbase + (row * SH_STRIDE + s * 8) * 2,
                 Ain + (size_t)(blockIdx.x * GR + row) * 8 + s);
        }
        asm volatile("cp.async.commit_group;");
    }

    int buf = 0;
    for (int tile = blockIdx.x; tile < TILES; tile += gridDim.x, buf ^= 1) {
        int nxt = tile + gridDim.x;
        if (nxt < TILES) {
            unsigned sbase = (unsigned)__cvta_generic_to_shared(&sA[buf ^ 1][0]);
            #pragma unroll
            for (int j = 0; j < 4; j++) {
                int i = t + 256 * j;
                int row = i >> 3, s = i & 7;
                cp16(sbase + (row * SH_STRIDE + s * 8) * 2,
                     Ain + (size_t)(nxt * GR + row) * 8 + s);
            }
            asm volatile("cp.async.commit_group;");
            asm volatile("cp.async.wait_group 1;");
        } else {
            asm volatile("cp.async.wait_group 0;");
        }
        __syncthreads();                        // sA[buf] ready

        float c[8][4];
        #pragma unroll
        for (int nt = 0; nt < 8; nt++)
            #pragma unroll
            for (int p = 0; p < 4; p++) c[nt][p] = 0.f;

        const half* arow0 = sA[buf] + (warp * 16 + g) * SH_STRIDE;
        const half* arow8 = arow0 + 8 * SH_STRIDE;
        #pragma unroll
        for (int kc = 0; kc < 4; kc++) {
            int k0 = kc * 16 + tg * 2;
            unsigned a0 = *(const unsigned*)(arow0 + k0);
            unsigned a1 = *(const unsigned*)(arow8 + k0);
            unsigned a2 = *(const unsigned*)(arow0 + k0 + 8);
            unsigned a3 = *(const unsigned*)(arow8 + k0 + 8);
            #pragma unroll
            for (int nt = 0; nt < 8; nt++) {
                const half* brow = sB + (nt * 8 + g) * SH_STRIDE + k0;
                unsigned b0 = *(const unsigned*)(brow);
                unsigned b1 = *(const unsigned*)(brow + 8);
                mma_16816(c[nt], a0, a1, a2, a3, b0, b1);
            }
        }

        // direct register -> global epilogue (half2 stores)
        int gr0 = tile * GR + warp * 16 + g;
        #pragma unroll
        for (int nt = 0; nt < 8; nt++) {
            half2 h01 = __floats2half2_rn(c[nt][0], c[nt][1]);
            half2 h23 = __floats2half2_rn(c[nt][2], c[nt][3]);
            if (gr0 < N_NODES)
                *(half2*)(Aout + (size_t)gr0 * 64 + nt * 8 + tg * 2) = h01;
            if (gr0 + 8 < N_NODES)
                *(half2*)(Aout + (size_t)(gr0 + 8) * 64 + nt * 8 + tg * 2) = h23;
        }
        __syncthreads();                        // all reads of sA[buf] done before reuse
    }
}

// ---------------------------------------------------------------------------
// CSR aggregation: 8 threads/node, LDG.128 fp16 gathers, unroll-4.
// mode 0: relu + half store to hdst.  mode 1: red.v4 into g_pool (layer 3).
// ---------------------------------------------------------------------------
__device__ __forceinline__ void acc8h(float* a, uint4 u, float n) {
    float2 f0 = __half22float2(*(half2*)&u.x);
    float2 f1 = __half22float2(*(half2*)&u.y);
    float2 f2 = __half22float2(*(half2*)&u.z);
    float2 f3 = __half22float2(*(half2*)&u.w);
    a[0] += f0.x * n; a[1] += f0.y * n;
    a[2] += f1.x * n; a[3] += f1.y * n;
    a[4] += f2.x * n; a[5] += f2.y * n;
    a[6] += f3.x * n; a[7] += f3.y * n;
}

__global__ __launch_bounds__(256) void agg_kernel(const float* __restrict__ bias,
                                                  const void* __restrict__ batch,
                                                  const uint4* __restrict__ hsrc,
                                                  uint4* __restrict__ hdst,
                                                  int mode) {
    int gid = blockIdx.x * blockDim.x + threadIdx.x;
    if (gid >= N_NODES * 8) return;
    int node = gid >> 3, s = gid & 7;
    int j   = g_off[node];
    int end = g_off[node + 1];

    float a[8] = {0.f, 0.f, 0.f, 0.f, 0.f, 0.f, 0.f, 0.f};
    for (; j + 4 <= end; j += 4) {
        float2 e0 = g_edge[j],     e1 = g_edge[j + 1];
        float2 e2 = g_edge[j + 2], e3 = g_edge[j + 3];
        uint4 u0 = hsrc[(__float_as_int(e0.x) << 3) + s];
        uint4 u1 = hsrc[(__float_as_int(e1.x) << 3) + s];
        uint4 u2 = hsrc[(__float_as_int(e2.x) << 3) + s];
        uint4 u3 = hsrc[(__float_as_int(e3.x) << 3) + s];
        acc8h(a, u0, e0.y);
        acc8h(a, u1, e1.y);
        acc8h(a, u2, e2.y);
        acc8h(a, u3, e3.y);
    }
    for (; j < end; j++) {
        float2 e0 = g_edge[j];
        acc8h(a, hsrc[(__float_as_int(e0.x) << 3) + s], e0.y);
    }
    float di = g_dinv[node];
    acc8h(a, hsrc[(node << 3) + s], di * di);
    const float4* b4 = (const float4*)(bias + s * 8);
    float4 bl = b4[0], bh = b4[1];
    a[0] += bl.x; a[1] += bl.y; a[2] += bl.z; a[3] += bl.w;
    a[4] += bh.x; a[5] += bh.y; a[6] += bh.z; a[7] += bh.w;

    if (mode) {
        int bg = load_bat(batch, node);
        float* dst = &g_pool[bg * D + s * 8];
        red_add_v4(dst,     make_float4(a[0], a[1], a[2], a[3]));
        red_add_v4(dst + 4, make_float4(a[4], a[5], a[6], a[7]));
    } else {
        #pragma unroll
        for (int i = 0; i < 8; i++) a[i] = fmaxf(a[i], 0.f);
        half2 h0 = __floats2half2_rn(a[0], a[1]);
        half2 h1 = __floats2half2_rn(a[2], a[3]);
        half2 h2 = __floats2half2_rn(a[4], a[5]);
        half2 h3 = __floats2half2_rn(a[6], a[7]);
        uint4 u;
        u.x = *(unsigned*)&h0; u.y = *(unsigned*)&h1;
        u.z = *(unsigned*)&h2; u.w = *(unsigned*)&h3;
        hdst[gid] = u;
    }
}

__global__ void final_kernel(const float* __restrict__ linW,
                             const float* __restrict__ linb,
                             float* __restrict__ out) {
    int id = blockIdx.x * blockDim.x + threadIdx.x;
    if (id >= N_GRAPHS * N_CLASSES) return;
    int b = id / N_CLASSES, c = id % N_CLASSES;
    int cnt = g_lb[b + 1] - g_lb[b];
    float inv = 1.0f / fmaxf((float)cnt, 1.0f);
    float acc = linb[c];
    #pragma unroll
    for (int d = 0; d < D; d++)
        acc += (g_pool[b * D + d] * inv) * linW[d * N_CLASSES + c];
    out[id] = acc;
}

extern "C" void kernel_launch(void* const* d_in, const int* in_sizes, int n_in,
                              void* d_out, int out_size) {
    const float* x    = (const float*)d_in[0];
    const void*  ei   = d_in[1];
    const void*  bat  = d_in[2];
    const float* W1   = (const float*)d_in[3];
    const float* b1   = (const float*)d_in[4];
    const float* W2   = (const float*)d_in[5];
    const float* b2   = (const float*)d_in[6];
    const float* W3   = (const float*)d_in[7];
    const float* b3   = (const float*)d_in[8];
    const float* linW = (const float*)d_in[9];
    const float* linb = (const float*)d_in[10];
    float* out = (float*)d_out;

    void *deg_p, *hh_p, *hh2_p, *wh_p;
    cudaGetSymbolAddress(&deg_p, g_deg);
    cudaGetSymbolAddress(&hh_p,  g_hh);
    cudaGetSymbolAddress(&hh2_p, g_hh2);
    cudaGetSymbolAddress(&wh_p,  g_wh);
    uint4* bufA = (uint4*)hh_p;      // g_hh
    uint4* bufB = (uint4*)hh2_p;     // g_hh2
    const unsigned* wh = (const unsigned*)wh_p;

    cudaMemsetAsync(deg_p, 0, N_NODES * sizeof(int));

    const int NODE8 = (N_NODES * 8 + 255) / 256;

    detect_kernel<<<1, 256>>>((const int*)ei, (const int*)bat, W1, W2, W3);
    deglb_kernel<<<(N_EDGES + 255) / 256, 256>>>(ei, bat, x, bufB);  // x -> half in bufB
    scan1_kernel<<<SCAN_NB, 256>>>();
    gemm_kernel<<<391, 256>>>(bufB, (half*)bufA, wh + 0 * 2048);     // profiled slot
    scan3_kernel<<<SCAN_NB, 256>>>();
    fill_kernel<<<(N_EDGES + 255) / 256, 256>>>(ei);

    agg_kernel<<<NODE8, 256>>>(b1, bat, bufA, bufB, 0);              // relu half -> bufB
    gemm_kernel<<<391, 256>>>(bufB, (half*)bufA, wh + 1 * 2048);
    agg_kernel<<<NODE8, 256>>>(b2, bat, bufA, bufB, 0);
    gemm_kernel<<<391, 256>>>(bufB, (half*)bufA, wh + 2 * 2048);
    agg_kernel<<<NODE8, 256>>>(b3, bat, bufA, (uint4*)nullptr, 1);   // fused pool

    final_kernel<<<(N_GRAPHS * N_CLASSES + 255) / 256, 256>>>(linW, linb, out);
}

// round 14
// speedup vs baseline: 1.3347x; 1.0213x over previous
#include <cuda_runtime.h>
#include <cuda_fp16.h>
#include <stdint.h>

#define N_NODES   100000
#define N_EDGES   1200000
#define N_GRAPHS  128
#define D         64
#define N_CLASSES 10

#define SCAN_NB   ((N_NODES + 1023) / 1024)

#define GR        128                     // gemm tile rows
#define TILES     ((N_NODES + GR - 1) / GR)   // 782
#define PAD_ROWS  (TILES * GR)                // 100096

// ---- device scratch (allocation-free) ----
__device__ __align__(128) unsigned g_hh [PAD_ROWS * 32];  // half feature buf A (128B/row)
__device__ __align__(128) unsigned g_hh2[PAD_ROWS * 32];  // half feature buf B
__device__ __align__(128) unsigned g_wh[3 * 2048];        // W1..W3 half2, n-major [n][k/2]
__device__ __align__(128) float  g_dinv[N_NODES];
__device__ __align__(128) int    g_deg[N_NODES];
__device__ __align__(128) int    g_off[N_NODES + 1];
__device__ __align__(128) int    g_cursor[N_NODES];
__device__ __align__(128) float2 g_edge[N_EDGES];         // {src_as_bits, norm}
__device__ __align__(128) int    g_bsum[SCAN_NB];
__device__ __align__(128) float  g_pool[N_GRAPHS * D];
__device__ int g_lb[N_GRAPHS + 1];
__device__ int g_ei64;
__device__ int g_bat64;

__device__ __forceinline__ void red_add_v4(float* addr, float4 v) {
    asm volatile("red.global.add.v4.f32 [%0], {%1, %2, %3, %4};"
                 :: "l"(addr), "f"(v.x), "f"(v.y), "f"(v.z), "f"(v.w)
                 : "memory");
}

// m16n8k16 HMMA, f16 in / f32 accum
__device__ __forceinline__ void mma_16816(float* c,
                                          unsigned a0, unsigned a1,
                                          unsigned a2, unsigned a3,
                                          unsigned b0, unsigned b1) {
    asm volatile(
        "mma.sync.aligned.m16n8k16.row.col.f32.f16.f16.f32 "
        "{%0,%1,%2,%3}, {%4,%5,%6,%7}, {%8,%9}, {%0,%1,%2,%3};"
        : "+f"(c[0]), "+f"(c[1]), "+f"(c[2]), "+f"(c[3])
        : "r"(a0), "r"(a1), "r"(a2), "r"(a3), "r"(b0), "r"(b1));
}

__device__ __forceinline__ void cp16(unsigned dst_smem, const void* src) {
    asm volatile("cp.async.cg.shared.global [%0], [%1], 16;"
                 :: "r"(dst_smem), "l"(src));
}

// ---------------------------------------------------------------------------
// detect dtypes + zero pool + convert W1..W3 to half (n-major) once
// ---------------------------------------------------------------------------
__global__ void detect_kernel(const int* ei_words, const int* bat_words,
                              const float* __restrict__ W1,
                              const float* __restrict__ W2,
                              const float* __restrict__ W3) {
    int v = 0;
    for (int i = threadIdx.x; i < 2048; i += blockDim.x) v |= ei_words[2 * i + 1];
    int ei_nz = __syncthreads_or(v != 0);
    int w = 0;
    for (int i = threadIdx.x; i < 2048; i += blockDim.x) {
        int wi = N_NODES - 1 - 2 * i;
        wi -= (1 - (wi & 1));
        if (wi >= 1) w |= bat_words[wi];
    }
    int bat_nz = __syncthreads_or(w != 0);
    if (threadIdx.x == 0) { g_ei64 = ei_nz ? 0 : 1; g_bat64 = bat_nz ? 0 : 1; }
    for (int i = threadIdx.x; i < N_GRAPHS * D; i += blockDim.x) g_pool[i] = 0.f;

    const float* Ws[3] = {W1, W2, W3};
    #pragma unroll
    for (int m = 0; m < 3; m++) {
        const float* W = Ws[m];
        for (int i = threadIdx.x; i < 2048; i += blockDim.x) {
            int n = i >> 5, kp = i & 31, k = kp * 2;
            half2 h = __floats2half2_rn(W[k * 64 + n], W[(k + 1) * 64 + n]);
            g_wh[m * 2048 + i] = *(unsigned*)&h;
        }
    }
}

__device__ __forceinline__ int load_ei(const void* p, long long i) {
    return g_ei64 ? (int)((const long long*)p)[i] : ((const int*)p)[i];
}
__device__ __forceinline__ int load_bat(const void* p, int i) {
    return g_bat64 ? (int)((const long long*)p)[i] : ((const int*)p)[i];
}

// ---------------------------------------------------------------------------
// deglb: degree atomics + graph boundaries + x fp32 -> half (padded rows)
// ---------------------------------------------------------------------------
__global__ void deglb_kernel(const void* __restrict__ ei,
                             const void* __restrict__ batch,
                             const float* __restrict__ x,
                             uint4* __restrict__ xh) {
    int e = blockIdx.x * blockDim.x + threadIdx.x;
    if (e < N_NODES) {
        int b0 = load_bat(batch, e);
        if (e == 0)
            for (int b = 0; b <= b0; b++) g_lb[b] = 0;
        int b1 = (e + 1 < N_NODES) ? load_bat(batch, e + 1) : N_GRAPHS;
        for (int b = b0 + 1; b <= b1; b++) g_lb[b] = e + 1;
    }
    if (e < PAD_ROWS * 8) {
        int gr = e >> 3, s = e & 7;
        uint4 u = make_uint4(0u, 0u, 0u, 0u);
        if (gr < N_NODES) {
            float4 v0 = ((const float4*)x)[gr * 16 + s * 2];
            float4 v1 = ((const float4*)x)[gr * 16 + s * 2 + 1];
            half2 h0 = __floats2half2_rn(v0.x, v0.y);
            half2 h1 = __floats2half2_rn(v0.z, v0.w);
            half2 h2 = __floats2half2_rn(v1.x, v1.y);
            half2 h3 = __floats2half2_rn(v1.z, v1.w);
            u.x = *(unsigned*)&h0; u.y = *(unsigned*)&h1;
            u.z = *(unsigned*)&h2; u.w = *(unsigned*)&h3;
        }
        xh[gr * 8 + s] = u;
    }
    if (e < N_EDGES)
        atomicAdd(&g_deg[load_ei(ei, (long long)N_EDGES + e)], 1);
}

__global__ void scan1_kernel() {
    __shared__ int s[256];
    int t = threadIdx.x;
    int base = blockIdx.x * 1024 + t * 4;
    int sum = 0;
    #pragma unroll
    for (int j = 0; j < 4; j++) { int i = base + j; if (i < N_NODES) sum += g_deg[i]; }
    s[t] = sum; __syncthreads();
    for (int o = 128; o > 0; o >>= 1) { if (t < o) s[t] += s[t + o]; __syncthreads(); }
    if (t == 0) g_bsum[blockIdx.x] = s[0];
}

__global__ void scan3_kernel() {
    __shared__ int sb[128];
    __shared__ int ts[256];
    int t = threadIdx.x;

    if (t < 128) sb[t] = (t < SCAN_NB) ? g_bsum[t] : 0;
    __syncthreads();
    for (int o = 1; o < 128; o <<= 1) {
        int v = (t < 128 && t >= o) ? sb[t - o] : 0;
        __syncthreads();
        if (t < 128) sb[t] += v;
        __syncthreads();
    }
    int blockpre = (blockIdx.x == 0) ? 0 : sb[blockIdx.x - 1];

    int base = blockIdx.x * 1024 + t * 4;
    int v[4];
    #pragma unroll
    for (int j = 0; j < 4; j++) v[j] = (base + j < N_NODES) ? g_deg[base + j] : 0;
    ts[t] = v[0] + v[1] + v[2] + v[3]; __syncthreads();
    for (int o = 1; o < 256; o <<= 1) {
        int x = (t >= o) ? ts[t - o] : 0;
        __syncthreads(); ts[t] += x; __syncthreads();
    }
    int pre = blockpre + ((t == 0) ? 0 : ts[t - 1]);
    #pragma unroll
    for (int j = 0; j < 4; j++) {
        int i = base + j;
        if (i < N_NODES) {
            g_off[i] = pre; g_cursor[i] = pre;
            g_dinv[i] = rsqrtf((float)v[j] + 1.0f);
        }
        pre += v[j];
    }
    if (blockIdx.x == 0 && t == 0) g_off[N_NODES] = N_EDGES;
}

__global__ void fill_kernel(const void* __restrict__ ei) {
    int e = blockIdx.x * blockDim.x + threadIdx.x;
    if (e >= N_EDGES) return;
    int r = load_ei(ei, e);
    int c = load_ei(ei, (long long)N_EDGES + e);
    int pos = atomicAdd(&g_cursor[c], 1);
    g_edge[pos] = make_float2(__int_as_float(r), g_dinv[r] * g_dinv[c]);
}

// ---------------------------------------------------------------------------
// Persistent double-buffered HMMA GEMM (layer 1 only): Aout = Ain @ W.
// ---------------------------------------------------------------------------
#define SH_STRIDE 72
__global__ __launch_bounds__(256) void gemm_kernel(const uint4* __restrict__ Ain,
                                                   half* __restrict__ Aout,
                                                   const unsigned* __restrict__ wh) {
    __shared__ __align__(16) half sA[2][GR * SH_STRIDE];
    __shared__ __align__(16) half sB[64 * SH_STRIDE];
    const int t = threadIdx.x;

    for (int i = t; i < 512; i += 256) {
        int n = i >> 3, s = i & 7;
        *(uint4*)&sB[n * SH_STRIDE + s * 8] = ((const uint4*)wh)[i];
    }

    const int warp = t >> 5, lane = t & 31;
    const int g = lane >> 2, tg = lane & 3;

    {
        unsigned sbase = (unsigned)__cvta_generic_to_shared(&sA[0][0]);
        #pragma unroll
        for (int j = 0; j < 4; j++) {
            int i = t + 256 * j;
            int row = i >> 3, s = i & 7;
            cp16(sbase + (row * SH_STRIDE + s * 8) * 2,
                 Ain + (size_t)(blockIdx.x * GR + row) * 8 + s);
        }
        asm volatile("cp.async.commit_group;");
    }

    int buf = 0;
    for (int tile = blockIdx.x; tile < TILES; tile += gridDim.x, buf ^= 1) {
        int nxt = tile + gridDim.x;
        if (nxt < TILES) {
            unsigned sbase = (unsigned)__cvta_generic_to_shared(&sA[buf ^ 1][0]);
            #pragma unroll
            for (int j = 0; j < 4; j++) {
                int i = t + 256 * j;
                int row = i >> 3, s = i & 7;
                cp16(sbase + (row * SH_STRIDE + s * 8) * 2,
                     Ain + (size_t)(nxt * GR + row) * 8 + s);
            }
            asm volatile("cp.async.commit_group;");
            asm volatile("cp.async.wait_group 1;");
        } else {
            asm volatile("cp.async.wait_group 0;");
        }
        __syncthreads();

        float c[8][4];
        #pragma unroll
        for (int nt = 0; nt < 8; nt++)
            #pragma unroll
            for (int p = 0; p < 4; p++) c[nt][p] = 0.f;

        const half* arow0 = sA[buf] + (warp * 16 + g) * SH_STRIDE;
        const half* arow8 = arow0 + 8 * SH_STRIDE;
        #pragma unroll
        for (int kc = 0; kc < 4; kc++) {
            int k0 = kc * 16 + tg * 2;
            unsigned a0 = *(const unsigned*)(arow0 + k0);
            unsigned a1 = *(const unsigned*)(arow8 + k0);
            unsigned a2 = *(const unsigned*)(arow0 + k0 + 8);
            unsigned a3 = *(const unsigned*)(arow8 + k0 + 8);
            #pragma unroll
            for (int nt = 0; nt < 8; nt++) {
                const half* brow = sB + (nt * 8 + g) * SH_STRIDE + k0;
                unsigned b0 = *(const unsigned*)(brow);
                unsigned b1 = *(const unsigned*)(brow + 8);
                mma_16816(c[nt], a0, a1, a2, a3, b0, b1);
            }
        }

        int gr0 = tile * GR + warp * 16 + g;
        #pragma unroll
        for (int nt = 0; nt < 8; nt++) {
            half2 h01 = __floats2half2_rn(c[nt][0], c[nt][1]);
            half2 h23 = __floats2half2_rn(c[nt][2], c[nt][3]);
            if (gr0 < N_NODES)
                *(half2*)(Aout + (size_t)gr0 * 64 + nt * 8 + tg * 2) = h01;
            if (gr0 + 8 < N_NODES)
                *(half2*)(Aout + (size_t)(gr0 + 8) * 64 + nt * 8 + tg * 2) = h23;
        }
        __syncthreads();
    }
}

// ---------------------------------------------------------------------------
// fp16 gather accumulate helper
// ---------------------------------------------------------------------------
__device__ __forceinline__ void acc8h(float* a, uint4 u, float n) {
    float2 f0 = __half22float2(*(half2*)&u.x);
    float2 f1 = __half22float2(*(half2*)&u.y);
    float2 f2 = __half22float2(*(half2*)&u.z);
    float2 f3 = __half22float2(*(half2*)&u.w);
    a[0] += f0.x * n; a[1] += f0.y * n;
    a[2] += f1.x * n; a[3] += f1.y * n;
    a[4] += f2.x * n; a[5] += f2.y * n;
    a[6] += f3.x * n; a[7] += f3.y * n;
}

// ---------------------------------------------------------------------------
// FUSED agg + GEMM (layers 2,3): aggregate 128 nodes into the smem A-tile
// (relu'd), then HMMA with W, write M_next. No intermediate global buffer.
// ---------------------------------------------------------------------------
__global__ __launch_bounds__(256) void fused_kernel(const uint4* __restrict__ hsrc,
                                                    half* __restrict__ Mout,
                                                    const unsigned* __restrict__ wh,
                                                    const float* __restrict__ bias) {
    __shared__ __align__(16) half sA[GR * SH_STRIDE];   // agg result tile
    __shared__ __align__(16) half sB[64 * SH_STRIDE];
    const int t = threadIdx.x;
    const int base = blockIdx.x * GR;
    const int s = t & 7;

    for (int i = t; i < 512; i += 256) {
        int n = i >> 3, w = i & 7;
        *(uint4*)&sB[n * SH_STRIDE + w * 8] = ((const uint4*)wh)[i];
    }

    const float4* b4 = (const float4*)(bias + s * 8);
    const float4 bl = b4[0], bh = b4[1];

    // --- aggregation phase: 8 threads/node, 4 node-passes per thread ---
    #pragma unroll 1
    for (int pass = 0; pass < 4; pass++) {
        int row = (t >> 3) + pass * 32;
        int node = base + row;
        uint4 u = make_uint4(0u, 0u, 0u, 0u);
        if (node < N_NODES) {
            int j   = g_off[node];
            int end = g_off[node + 1];
            float a[8] = {0.f, 0.f, 0.f, 0.f, 0.f, 0.f, 0.f, 0.f};
            for (; j + 4 <= end; j += 4) {
                float2 e0 = g_edge[j],     e1 = g_edge[j + 1];
                float2 e2 = g_edge[j + 2], e3 = g_edge[j + 3];
                uint4 u0 = hsrc[(__float_as_int(e0.x) << 3) + s];
                uint4 u1 = hsrc[(__float_as_int(e1.x) << 3) + s];
                uint4 u2 = hsrc[(__float_as_int(e2.x) << 3) + s];
                uint4 u3 = hsrc[(__float_as_int(e3.x) << 3) + s];
                acc8h(a, u0, e0.y);
                acc8h(a, u1, e1.y);
                acc8h(a, u2, e2.y);
                acc8h(a, u3, e3.y);
            }
            for (; j < end; j++) {
                float2 e0 = g_edge[j];
                acc8h(a, hsrc[(__float_as_int(e0.x) << 3) + s], e0.y);
            }
            float di = g_dinv[node];
            acc8h(a, hsrc[(node << 3) + s], di * di);
            a[0] += bl.x; a[1] += bl.y; a[2] += bl.z; a[3] += bl.w;
            a[4] += bh.x; a[5] += bh.y; a[6] += bh.z; a[7] += bh.w;
            #pragma unroll
            for (int i = 0; i < 8; i++) a[i] = fmaxf(a[i], 0.f);
            half2 h0 = __floats2half2_rn(a[0], a[1]);
            half2 h1 = __floats2half2_rn(a[2], a[3]);
            half2 h2 = __floats2half2_rn(a[4], a[5]);
            half2 h3 = __floats2half2_rn(a[6], a[7]);
            u.x = *(unsigned*)&h0; u.y = *(unsigned*)&h1;
            u.z = *(unsigned*)&h2; u.w = *(unsigned*)&h3;
        }
        *(uint4*)&sA[row * SH_STRIDE + s * 8] = u;
    }
    __syncthreads();

    // --- MMA phase ---
    const int warp = t >> 5, lane = t & 31;
    const int g = lane >> 2, tg = lane & 3;

    float c[8][4];
    #pragma unroll
    for (int nt = 0; nt < 8; nt++)
        #pragma unroll
        for (int p = 0; p < 4; p++) c[nt][p] = 0.f;

    const half* arow0 = sA + (warp * 16 + g) * SH_STRIDE;
    const half* arow8 = arow0 + 8 * SH_STRIDE;
    #pragma unroll
    for (int kc = 0; kc < 4; kc++) {
        int k0 = kc * 16 + tg * 2;
        unsigned a0 = *(const unsigned*)(arow0 + k0);
        unsigned a1 = *(const unsigned*)(arow8 + k0);
        unsigned a2 = *(const unsigned*)(arow0 + k0 + 8);
        unsigned a3 = *(const unsigned*)(arow8 + k0 + 8);
        #pragma unroll
        for (int nt = 0; nt < 8; nt++) {
            const half* brow = sB + (nt * 8 + g) * SH_STRIDE + k0;
            unsigned b0 = *(const unsigned*)(brow);
            unsigned b1 = *(const unsigned*)(brow + 8);
            mma_16816(c[nt], a0, a1, a2, a3, b0, b1);
        }
    }

    int gr0 = base + warp * 16 + g;
    #pragma unroll
    for (int nt = 0; nt < 8; nt++) {
        half2 h01 = __floats2half2_rn(c[nt][0], c[nt][1]);
        half2 h23 = __floats2half2_rn(c[nt][2], c[nt][3]);
        if (gr0 < N_NODES)
            *(half2*)(Mout + (size_t)gr0 * 64 + nt * 8 + tg * 2) = h01;
        if (gr0 + 8 < N_NODES)
            *(half2*)(Mout + (size_t)(gr0 + 8) * 64 + nt * 8 + tg * 2) = h23;
    }
}

// ---------------------------------------------------------------------------
// agg (layer 3): aggregate + bias, red.v4 into g_pool.
// ---------------------------------------------------------------------------
__global__ __launch_bounds__(256) void agg_kernel(const float* __restrict__ bias,
                                                  const void* __restrict__ batch,
                                                  const uint4* __restrict__ hsrc) {
    int gid = blockIdx.x * blockDim.x + threadIdx.x;
    if (gid >= N_NODES * 8) return;
    int node = gid >> 3, s = gid & 7;
    int j   = g_off[node];
    int end = g_off[node + 1];

    float a[8] = {0.f, 0.f, 0.f, 0.f, 0.f, 0.f, 0.f, 0.f};
    for (; j + 4 <= end; j += 4) {
        float2 e0 = g_edge[j],     e1 = g_edge[j + 1];
        float2 e2 = g_edge[j + 2], e3 = g_edge[j + 3];
        uint4 u0 = hsrc[(__float_as_int(e0.x) << 3) + s];
        uint4 u1 = hsrc[(__float_as_int(e1.x) << 3) + s];
        uint4 u2 = hsrc[(__float_as_int(e2.x) << 3) + s];
        uint4 u3 = hsrc[(__float_as_int(e3.x) << 3) + s];
        acc8h(a, u0, e0.y);
        acc8h(a, u1, e1.y);
        acc8h(a, u2, e2.y);
        acc8h(a, u3, e3.y);
    }
    for (; j < end; j++) {
        float2 e0 = g_edge[j];
        acc8h(a, hsrc[(__float_as_int(e0.x) << 3) + s], e0.y);
    }
    float di = g_dinv[node];
    acc8h(a, hsrc[(node << 3) + s], di * di);
    const float4* b4 = (const float4*)(bias + s * 8);
    float4 bl = b4[0], bh = b4[1];
    a[0] += bl.x; a[1] += bl.y; a[2] += bl.z; a[3] += bl.w;
    a[4] += bh.x; a[5] += bh.y; a[6] += bh.z; a[7] += bh.w;

    int bg = load_bat(batch, node);
    float* dst = &g_pool[bg * D + s * 8];
    red_add_v4(dst,     make_float4(a[0], a[1], a[2], a[3]));
    red_add_v4(dst + 4, make_float4(a[4], a[5], a[6], a[7]));
}

__global__ void final_kernel(const float* __restrict__ linW,
                             const float* __restrict__ linb,
                             float* __restrict__ out) {
    int id = blockIdx.x * blockDim.x + threadIdx.x;
    if (id >= N_GRAPHS * N_CLASSES) return;
    int b = id / N_CLASSES, c = id % N_CLASSES;
    int cnt = g_lb[b + 1] - g_lb[b];
    float inv = 1.0f / fmaxf((float)cnt, 1.0f);
    float acc = linb[c];
    #pragma unroll
    for (int d = 0; d < D; d++)
        acc += (g_pool[b * D + d] * inv) * linW[d * N_CLASSES + c];
    out[id] = acc;
}

extern "C" void kernel_launch(void* const* d_in, const int* in_sizes, int n_in,
                              void* d_out, int out_size) {
    const float* x    = (const float*)d_in[0];
    const void*  ei   = d_in[1];
    const void*  bat  = d_in[2];
    const float* W1   = (const float*)d_in[3];
    const float* b1   = (const float*)d_in[4];
    const float* W2   = (const float*)d_in[5];
    const float* b2   = (const float*)d_in[6];
    const float* W3   = (const float*)d_in[7];
    const float* b3   = (const float*)d_in[8];
    const float* linW = (const float*)d_in[9];
    const float* linb = (const float*)d_in[10];
    float* out = (float*)d_out;

    void *deg_p, *hh_p, *hh2_p, *wh_p;
    cudaGetSymbolAddress(&deg_p, g_deg);
    cudaGetSymbolAddress(&hh_p,  g_hh);
    cudaGetSymbolAddress(&hh2_p, g_hh2);
    cudaGetSymbolAddress(&wh_p,  g_wh);
    uint4* bufA = (uint4*)hh_p;
    uint4* bufB = (uint4*)hh2_p;
    const unsigned* wh = (const unsigned*)wh_p;

    cudaMemsetAsync(deg_p, 0, N_NODES * sizeof(int));

    const int NODE8 = (N_NODES * 8 + 255) / 256;

    detect_kernel<<<1, 256>>>((const int*)ei, (const int*)bat, W1, W2, W3);
    deglb_kernel<<<(N_EDGES + 255) / 256, 256>>>(ei, bat, x, bufB);  // x -> half in bufB
    scan1_kernel<<<SCAN_NB, 256>>>();
    gemm_kernel<<<391, 256>>>(bufB, (half*)bufA, wh + 0 * 2048);     // M1 -> bufA (profiled)
    scan3_kernel<<<SCAN_NB, 256>>>();
    fill_kernel<<<(N_EDGES + 255) / 256, 256>>>(ei);

    // layer 2: agg(M1,b1)+relu fused with gemm W2 -> M2 in bufB
    fused_kernel<<<TILES, 256>>>(bufA, (half*)bufB, wh + 1 * 2048, b1);
    // layer 3: agg(M2,b2)+relu fused with gemm W3 -> M3 in bufA
    fused_kernel<<<TILES, 256>>>(bufB, (half*)bufA, wh + 2 * 2048, b2);
    // final aggregation straight into pool
    agg_kernel<<<NODE8, 256>>>(b3, bat, bufA);

    final_kernel<<<(N_GRAPHS * N_CLASSES + 255) / 256, 256>>>(linW, linb, out);
}

// round 15
// speedup vs baseline: 1.3467x; 1.0090x over previous
#include <cuda_runtime.h>
#include <cuda_fp16.h>
#include <stdint.h>

#define N_NODES   100000
#define N_EDGES   1200000
#define N_GRAPHS  128
#define D         64
#define N_CLASSES 10

#define SCAN_NB   ((N_NODES + 1023) / 1024)

#define GR        128                     // gemm tile rows
#define TILES     ((N_NODES + GR - 1) / GR)   // 782
#define PAD_ROWS  (TILES * GR)                // 100096

// ---- device scratch (allocation-free) ----
__device__ __align__(128) unsigned g_hh [PAD_ROWS * 32];  // half feature buf A (128B/row)
__device__ __align__(128) unsigned g_hh2[PAD_ROWS * 32];  // half feature buf B
__device__ __align__(128) unsigned g_wh[3 * 2048];        // W1..W3 half2, n-major [n][k/2]
__device__ __align__(128) float  g_dinv[N_NODES];
__device__ __align__(128) int    g_deg[N_NODES];
__device__ __align__(128) int    g_off[N_NODES + 1];
__device__ __align__(128) int    g_cursor[N_NODES];
__device__ __align__(128) float2 g_edge[N_EDGES];         // {src_as_bits, norm}
__device__ __align__(128) int    g_bsum[SCAN_NB];
__device__ __align__(128) float  g_pool[N_GRAPHS * D];
__device__ int g_lb[N_GRAPHS + 1];
__device__ int g_ei64;
__device__ int g_bat64;

// ---- fork-join plumbing (created once at static init; no device allocs) ----
static cudaStream_t g_s2 = nullptr;
static cudaEvent_t  g_ev1 = nullptr, g_ev2 = nullptr;
namespace {
struct _StreamInit {
    _StreamInit() {
        if (cudaStreamCreateWithFlags(&g_s2, cudaStreamNonBlocking) != cudaSuccess) g_s2 = nullptr;
        if (cudaEventCreateWithFlags(&g_ev1, cudaEventDisableTiming) != cudaSuccess) g_ev1 = nullptr;
        if (cudaEventCreateWithFlags(&g_ev2, cudaEventDisableTiming) != cudaSuccess) g_ev2 = nullptr;
    }
};
_StreamInit _stream_init;
}

__device__ __forceinline__ void red_add_v4(float* addr, float4 v) {
    asm volatile("red.global.add.v4.f32 [%0], {%1, %2, %3, %4};"
                 :: "l"(addr), "f"(v.x), "f"(v.y), "f"(v.z), "f"(v.w)
                 : "memory");
}

// m16n8k16 HMMA, f16 in / f32 accum
__device__ __forceinline__ void mma_16816(float* c,
                                          unsigned a0, unsigned a1,
                                          unsigned a2, unsigned a3,
                                          unsigned b0, unsigned b1) {
    asm volatile(
        "mma.sync.aligned.m16n8k16.row.col.f32.f16.f16.f32 "
        "{%0,%1,%2,%3}, {%4,%5,%6,%7}, {%8,%9}, {%0,%1,%2,%3};"
        : "+f"(c[0]), "+f"(c[1]), "+f"(c[2]), "+f"(c[3])
        : "r"(a0), "r"(a1), "r"(a2), "r"(a3), "r"(b0), "r"(b1));
}

__device__ __forceinline__ void cp16(unsigned dst_smem, const void* src) {
    asm volatile("cp.async.cg.shared.global [%0], [%1], 16;"
                 :: "r"(dst_smem), "l"(src));
}

// ---------------------------------------------------------------------------
// convert x fp32 -> half padded rows (no dtype flags needed; runs first)
// ---------------------------------------------------------------------------
__global__ void convert_x_kernel(const float* __restrict__ x,
                                 uint4* __restrict__ xh) {
    int e = blockIdx.x * blockDim.x + threadIdx.x;
    if (e >= PAD_ROWS * 8) return;
    int gr = e >> 3, s = e & 7;
    uint4 u = make_uint4(0u, 0u, 0u, 0u);
    if (gr < N_NODES) {
        float4 v0 = ((const float4*)x)[gr * 16 + s * 2];
        float4 v1 = ((const float4*)x)[gr * 16 + s * 2 + 1];
        half2 h0 = __floats2half2_rn(v0.x, v0.y);
        half2 h1 = __floats2half2_rn(v0.z, v0.w);
        half2 h2 = __floats2half2_rn(v1.x, v1.y);
        half2 h3 = __floats2half2_rn(v1.z, v1.w);
        u.x = *(unsigned*)&h0; u.y = *(unsigned*)&h1;
        u.z = *(unsigned*)&h2; u.w = *(unsigned*)&h3;
    }
    xh[gr * 8 + s] = u;
}

// ---------------------------------------------------------------------------
// detect (3 parallel blocks): b0 ei dtype, b1 batch dtype, b2 W convert + pool0
// ---------------------------------------------------------------------------
__global__ void detect_kernel(const int* ei_words, const int* bat_words,
                              const float* __restrict__ W1,
                              const float* __restrict__ W2,
                              const float* __restrict__ W3) {
    if (blockIdx.x == 0) {
        int v = 0;
        for (int i = threadIdx.x; i < 2048; i += blockDim.x) v |= ei_words[2 * i + 1];
        int nz = __syncthreads_or(v != 0);
        if (threadIdx.x == 0) g_ei64 = nz ? 0 : 1;
    } else if (blockIdx.x == 1) {
        int w = 0;
        for (int i = threadIdx.x; i < 2048; i += blockDim.x) {
            int wi = N_NODES - 1 - 2 * i;
            wi -= (1 - (wi & 1));
            if (wi >= 1) w |= bat_words[wi];
        }
        int nz = __syncthreads_or(w != 0);
        if (threadIdx.x == 0) g_bat64 = nz ? 0 : 1;
    } else {
        for (int i = threadIdx.x; i < N_GRAPHS * D; i += blockDim.x) g_pool[i] = 0.f;
        const float* Ws[3] = {W1, W2, W3};
        #pragma unroll
        for (int m = 0; m < 3; m++) {
            const float* W = Ws[m];
            for (int i = threadIdx.x; i < 2048; i += blockDim.x) {
                int n = i >> 5, kp = i & 31, k = kp * 2;
                half2 h = __floats2half2_rn(W[k * 64 + n], W[(k + 1) * 64 + n]);
                g_wh[m * 2048 + i] = *(unsigned*)&h;
            }
        }
    }
}

__device__ __forceinline__ int load_ei(const void* p, long long i) {
    return g_ei64 ? (int)((const long long*)p)[i] : ((const int*)p)[i];
}
__device__ __forceinline__ int load_bat(const void* p, int i) {
    return g_bat64 ? (int)((const long long*)p)[i] : ((const int*)p)[i];
}

// ---------------------------------------------------------------------------
// deglb: degree atomics + graph boundaries
// ---------------------------------------------------------------------------
__global__ void deglb_kernel(const void* __restrict__ ei,
                             const void* __restrict__ batch) {
    int e = blockIdx.x * blockDim.x + threadIdx.x;
    if (e < N_NODES) {
        int b0 = load_bat(batch, e);
        if (e == 0)
            for (int b = 0; b <= b0; b++) g_lb[b] = 0;
        int b1 = (e + 1 < N_NODES) ? load_bat(batch, e + 1) : N_GRAPHS;
        for (int b = b0 + 1; b <= b1; b++) g_lb[b] = e + 1;
    }
    if (e < N_EDGES)
        atomicAdd(&g_deg[load_ei(ei, (long long)N_EDGES + e)], 1);
}

__global__ void scan1_kernel() {
    __shared__ int s[256];
    int t = threadIdx.x;
    int base = blockIdx.x * 1024 + t * 4;
    int sum = 0;
    #pragma unroll
    for (int j = 0; j < 4; j++) { int i = base + j; if (i < N_NODES) sum += g_deg[i]; }
    s[t] = sum; __syncthreads();
    for (int o = 128; o > 0; o >>= 1) { if (t < o) s[t] += s[t + o]; __syncthreads(); }
    if (t == 0) g_bsum[blockIdx.x] = s[0];
}

__global__ void scan3_kernel() {
    __shared__ int sb[128];
    __shared__ int ts[256];
    int t = threadIdx.x;

    if (t < 128) sb[t] = (t < SCAN_NB) ? g_bsum[t] : 0;
    __syncthreads();
    for (int o = 1; o < 128; o <<= 1) {
        int v = (t < 128 && t >= o) ? sb[t - o] : 0;
        __syncthreads();
        if (t < 128) sb[t] += v;
        __syncthreads();
    }
    int blockpre = (blockIdx.x == 0) ? 0 : sb[blockIdx.x - 1];

    int base = blockIdx.x * 1024 + t * 4;
    int v[4];
    #pragma unroll
    for (int j = 0; j < 4; j++) v[j] = (base + j < N_NODES) ? g_deg[base + j] : 0;
    ts[t] = v[0] + v[1] + v[2] + v[3]; __syncthreads();
    for (int o = 1; o < 256; o <<= 1) {
        int x = (t >= o) ? ts[t - o] : 0;
        __syncthreads(); ts[t] += x; __syncthreads();
    }
    int pre = blockpre + ((t == 0) ? 0 : ts[t - 1]);
    #pragma unroll
    for (int j = 0; j < 4; j++) {
        int i = base + j;
        if (i < N_NODES) {
            g_off[i] = pre; g_cursor[i] = pre;
            g_dinv[i] = rsqrtf((float)v[j] + 1.0f);
        }
        pre += v[j];
    }
    if (blockIdx.x == 0 && t == 0) g_off[N_NODES] = N_EDGES;
}

__global__ void fill_kernel(const void* __restrict__ ei) {
    int e = blockIdx.x * blockDim.x + threadIdx.x;
    if (e >= N_EDGES) return;
    int r = load_ei(ei, e);
    int c = load_ei(ei, (long long)N_EDGES + e);
    int pos = atomicAdd(&g_cursor[c], 1);
    g_edge[pos] = make_float2(__int_as_float(r), g_dinv[r] * g_dinv[c]);
}

// ---------------------------------------------------------------------------
// Persistent double-buffered HMMA GEMM (layer 1): Aout = Ain @ W.
// ---------------------------------------------------------------------------
#define SH_STRIDE 72
__global__ __launch_bounds__(256) void gemm_kernel(const uint4* __restrict__ Ain,
                                                   half* __restrict__ Aout,
                                                   const unsigned* __restrict__ wh) {
    __shared__ __align__(16) half sA[2][GR * SH_STRIDE];
    __shared__ __align__(16) half sB[64 * SH_STRIDE];
    const int t = threadIdx.x;

    for (int i = t; i < 512; i += 256) {
        int n = i >> 3, s = i & 7;
        *(uint4*)&sB[n * SH_STRIDE + s * 8] = ((const uint4*)wh)[i];
    }

    const int warp = t >> 5, lane = t & 31;
    const int g = lane >> 2, tg = lane & 3;

    {
        unsigned sbase = (unsigned)__cvta_generic_to_shared(&sA[0][0]);
        #pragma unroll
        for (int j = 0; j < 4; j++) {
            int i = t + 256 * j;
            int row = i >> 3, s = i & 7;
            cp16(sbase + (row * SH_STRIDE + s * 8) * 2,
                 Ain + (size_t)(blockIdx.x * GR + row) * 8 + s);
        }
        asm volatile("cp.async.commit_group;");
    }

    int buf = 0;
    for (int tile = blockIdx.x; tile < TILES; tile += gridDim.x, buf ^= 1) {
        int nxt = tile + gridDim.x;
        if (nxt < TILES) {
            unsigned sbase = (unsigned)__cvta_generic_to_shared(&sA[buf ^ 1][0]);
            #pragma unroll
            for (int j = 0; j < 4; j++) {
                int i = t + 256 * j;
                int row = i >> 3, s = i & 7;
                cp16(sbase + (row * SH_STRIDE + s * 8) * 2,
                     Ain + (size_t)(nxt * GR + row) * 8 + s);
            }
            asm volatile("cp.async.commit_group;");
            asm volatile("cp.async.wait_group 1;");
        } else {
            asm volatile("cp.async.wait_group 0;");
        }
        __syncthreads();

        float c[8][4];
        #pragma unroll
        for (int nt = 0; nt < 8; nt++)
            #pragma unroll
            for (int p = 0; p < 4; p++) c[nt][p] = 0.f;

        const half* arow0 = sA[buf] + (warp * 16 + g) * SH_STRIDE;
        const half* arow8 = arow0 + 8 * SH_STRIDE;
        #pragma unroll
        for (int kc = 0; kc < 4; kc++) {
            int k0 = kc * 16 + tg * 2;
            unsigned a0 = *(const unsigned*)(arow0 + k0);
            unsigned a1 = *(const unsigned*)(arow8 + k0);
            unsigned a2 = *(const unsigned*)(arow0 + k0 + 8);
            unsigned a3 = *(const unsigned*)(arow8 + k0 + 8);
            #pragma unroll
            for (int nt = 0; nt < 8; nt++) {
                const half* brow = sB + (nt * 8 + g) * SH_STRIDE + k0;
                unsigned b0 = *(const unsigned*)(brow);
                unsigned b1 = *(const unsigned*)(brow + 8);
                mma_16816(c[nt], a0, a1, a2, a3, b0, b1);
            }
        }

        int gr0 = tile * GR + warp * 16 + g;
        #pragma unroll
        for (int nt = 0; nt < 8; nt++) {
            half2 h01 = __floats2half2_rn(c[nt][0], c[nt][1]);
            half2 h23 = __floats2half2_rn(c[nt][2], c[nt][3]);
            if (gr0 < N_NODES)
                *(half2*)(Aout + (size_t)gr0 * 64 + nt * 8 + tg * 2) = h01;
            if (gr0 + 8 < N_NODES)
                *(half2*)(Aout + (size_t)(gr0 + 8) * 64 + nt * 8 + tg * 2) = h23;
        }
        __syncthreads();
    }
}

// ---------------------------------------------------------------------------
// fp16 gather accumulate helper
// ---------------------------------------------------------------------------
__device__ __forceinline__ void acc8h(float* a, uint4 u, float n) {
    float2 f0 = __half22float2(*(half2*)&u.x);
    float2 f1 = __half22float2(*(half2*)&u.y);
    float2 f2 = __half22float2(*(half2*)&u.z);
    float2 f3 = __half22float2(*(half2*)&u.w);
    a[0] += f0.x * n; a[1] += f0.y * n;
    a[2] += f1.x * n; a[3] += f1.y * n;
    a[4] += f2.x * n; a[5] += f2.y * n;
    a[6] += f3.x * n; a[7] += f3.y * n;
}

// ---------------------------------------------------------------------------
// FUSED agg + GEMM (layers 2,3)
// ---------------------------------------------------------------------------
__global__ __launch_bounds__(256) void fused_kernel(const uint4* __restrict__ hsrc,
                                                    half* __restrict__ Mout,
                                                    const unsigned* __restrict__ wh,
                                                    const float* __restrict__ bias) {
    __shared__ __align__(16) half sA[GR * SH_STRIDE];
    __shared__ __align__(16) half sB[64 * SH_STRIDE];
    const int t = threadIdx.x;
    const int base = blockIdx.x * GR;
    const int s = t & 7;

    for (int i = t; i < 512; i += 256) {
        int n = i >> 3, w = i & 7;
        *(uint4*)&sB[n * SH_STRIDE + w * 8] = ((const uint4*)wh)[i];
    }

    const float4* b4 = (const float4*)(bias + s * 8);
    const float4 bl = b4[0], bh = b4[1];

    #pragma unroll 1
    for (int pass = 0; pass < 4; pass++) {
        int row = (t >> 3) + pass * 32;
        int node = base + row;
        uint4 u = make_uint4(0u, 0u, 0u, 0u);
        if (node < N_NODES) {
            int j   = g_off[node];
            int end = g_off[node + 1];
            float a[8] = {0.f, 0.f, 0.f, 0.f, 0.f, 0.f, 0.f, 0.f};
            for (; j + 4 <= end; j += 4) {
                float2 e0 = g_edge[j],     e1 = g_edge[j + 1];
                float2 e2 = g_edge[j + 2], e3 = g_edge[j + 3];
                uint4 u0 = hsrc[(__float_as_int(e0.x) << 3) + s];
                uint4 u1 = hsrc[(__float_as_int(e1.x) << 3) + s];
                uint4 u2 = hsrc[(__float_as_int(e2.x) << 3) + s];
                uint4 u3 = hsrc[(__float_as_int(e3.x) << 3) + s];
                acc8h(a, u0, e0.y);
                acc8h(a, u1, e1.y);
                acc8h(a, u2, e2.y);
                acc8h(a, u3, e3.y);
            }
            for (; j < end; j++) {
                float2 e0 = g_edge[j];
                acc8h(a, hsrc[(__float_as_int(e0.x) << 3) + s], e0.y);
            }
            float di = g_dinv[node];
            acc8h(a, hsrc[(node << 3) + s], di * di);
            a[0] += bl.x; a[1] += bl.y; a[2] += bl.z; a[3] += bl.w;
            a[4] += bh.x; a[5] += bh.y; a[6] += bh.z; a[7] += bh.w;
            #pragma unroll
            for (int i = 0; i < 8; i++) a[i] = fmaxf(a[i], 0.f);
            half2 h0 = __floats2half2_rn(a[0], a[1]);
            half2 h1 = __floats2half2_rn(a[2], a[3]);
            half2 h2 = __floats2half2_rn(a[4], a[5]);
            half2 h3 = __floats2half2_rn(a[6], a[7]);
            u.x = *(unsigned*)&h0; u.y = *(unsigned*)&h1;
            u.z = *(unsigned*)&h2; u.w = *(unsigned*)&h3;
        }
        *(uint4*)&sA[row * SH_STRIDE + s * 8] = u;
    }
    __syncthreads();

    const int warp = t >> 5, lane = t & 31;
    const int g = lane >> 2, tg = lane & 3;

    float c[8][4];
    #pragma unroll
    for (int nt = 0; nt < 8; nt++)
        #pragma unroll
        for (int p = 0; p < 4; p++) c[nt][p] = 0.f;

    const half* arow0 = sA + (warp * 16 + g) * SH_STRIDE;
    const half* arow8 = arow0 + 8 * SH_STRIDE;
    #pragma unroll
    for (int kc = 0; kc < 4; kc++) {
        int k0 = kc * 16 + tg * 2;
        unsigned a0 = *(const unsigned*)(arow0 + k0);
        unsigned a1 = *(const unsigned*)(arow8 + k0);
        unsigned a2 = *(const unsigned*)(arow0 + k0 + 8);
        unsigned a3 = *(const unsigned*)(arow8 + k0 + 8);
        #pragma unroll
        for (int nt = 0; nt < 8; nt++) {
            const half* brow = sB + (nt * 8 + g) * SH_STRIDE + k0;
            unsigned b0 = *(const unsigned*)(brow);
            unsigned b1 = *(const unsigned*)(brow + 8);
            mma_16816(c[nt], a0, a1, a2, a3, b0, b1);
        }
    }

    int gr0 = base + warp * 16 + g;
    #pragma unroll
    for (int nt = 0; nt < 8; nt++) {
        half2 h01 = __floats2half2_rn(c[nt][0], c[nt][1]);
        half2 h23 = __floats2half2_rn(c[nt][2], c[nt][3]);
        if (gr0 < N_NODES)
            *(half2*)(Mout + (size_t)gr0 * 64 + nt * 8 + tg * 2) = h01;
        if (gr0 + 8 < N_NODES)
            *(half2*)(Mout + (size_t)(gr0 + 8) * 64 + nt * 8 + tg * 2) = h23;
    }
}

// ---------------------------------------------------------------------------
// agg (layer 3): aggregate + bias, red.v4 into g_pool.
// ---------------------------------------------------------------------------
__global__ __launch_bounds__(256) void agg_kernel(const float* __restrict__ bias,
                                                  const void* __restrict__ batch,
                                                  const uint4* __restrict__ hsrc) {
    int gid = blockIdx.x * blockDim.x + threadIdx.x;
    if (gid >= N_NODES * 8) return;
    int node = gid >> 3, s = gid & 7;
    int j   = g_off[node];
    int end = g_off[node + 1];

    float a[8] = {0.f, 0.f, 0.f, 0.f, 0.f, 0.f, 0.f, 0.f};
    for (; j + 4 <= end; j += 4) {
        float2 e0 = g_edge[j],     e1 = g_edge[j + 1];
        float2 e2 = g_edge[j + 2], e3 = g_edge[j + 3];
        uint4 u0 = hsrc[(__float_as_int(e0.x) << 3) + s];
        uint4 u1 = hsrc[(__float_as_int(e1.x) << 3) + s];
        uint4 u2 = hsrc[(__float_as_int(e2.x) << 3) + s];
        uint4 u3 = hsrc[(__float_as_int(e3.x) << 3) + s];
        acc8h(a, u0, e0.y);
        acc8h(a, u1, e1.y);
        acc8h(a, u2, e2.y);
        acc8h(a, u3, e3.y);
    }
    for (; j < end; j++) {
        float2 e0 = g_edge[j];
        acc8h(a, hsrc[(__float_as_int(e0.x) << 3) + s], e0.y);
    }
    float di = g_dinv[node];
    acc8h(a, hsrc[(node << 3) + s], di * di);
    const float4* b4 = (const float4*)(bias + s * 8);
    float4 bl = b4[0], bh = b4[1];
    a[0] += bl.x; a[1] += bl.y; a[2] += bl.z; a[3] += bl.w;
    a[4] += bh.x; a[5] += bh.y; a[6] += bh.z; a[7] += bh.w;

    int bg = load_bat(batch, node);
    float* dst = &g_pool[bg * D + s * 8];
    red_add_v4(dst,     make_float4(a[0], a[1], a[2], a[3]));
    red_add_v4(dst + 4, make_float4(a[4], a[5], a[6], a[7]));
}

__global__ void final_kernel(const float* __restrict__ linW,
                             const float* __restrict__ linb,
                             float* __restrict__ out) {
    int id = blockIdx.x * blockDim.x + threadIdx.x;
    if (id >= N_GRAPHS * N_CLASSES) return;
    int b = id / N_CLASSES, c = id % N_CLASSES;
    int cnt = g_lb[b + 1] - g_lb[b];
    float inv = 1.0f / fmaxf((float)cnt, 1.0f);
    float acc = linb[c];
    #pragma unroll
    for (int d = 0; d < D; d++)
        acc += (g_pool[b * D + d] * inv) * linW[d * N_CLASSES + c];
    out[id] = acc;
}

extern "C" void kernel_launch(void* const* d_in, const int* in_sizes, int n_in,
                              void* d_out, int out_size) {
    const float* x    = (const float*)d_in[0];
    const void*  ei   = d_in[1];
    const void*  bat  = d_in[2];
    const float* W1   = (const float*)d_in[3];
    const float* b1   = (const float*)d_in[4];
    const float* W2   = (const float*)d_in[5];
    const float* b2   = (const float*)d_in[6];
    const float* W3   = (const float*)d_in[7];
    const float* b3   = (const float*)d_in[8];
    const float* linW = (const float*)d_in[9];
    const float* linb = (const float*)d_in[10];
    float* out = (float*)d_out;

    void *deg_p, *hh_p, *hh2_p, *wh_p;
    cudaGetSymbolAddress(&deg_p, g_deg);
    cudaGetSymbolAddress(&hh_p,  g_hh);
    cudaGetSymbolAddress(&hh2_p, g_hh2);
    cudaGetSymbolAddress(&wh_p,  g_wh);
    uint4* bufA = (uint4*)hh_p;
    uint4* bufB = (uint4*)hh2_p;
    const unsigned* wh = (const unsigned*)wh_p;

    const int NODE8 = (N_NODES * 8 + 255) / 256;
    const bool fork = (g_s2 != nullptr) && (g_ev1 != nullptr) && (g_ev2 != nullptr);

    cudaMemsetAsync(deg_p, 0, N_NODES * sizeof(int));
    convert_x_kernel<<<(PAD_ROWS * 8 + 255) / 256, 256>>>(x, bufB);   // x -> half (bufB)
    detect_kernel<<<3, 256>>>((const int*)ei, (const int*)bat, W1, W2, W3);

    if (fork) {
        cudaEventRecord(g_ev1, 0);
        cudaStreamWaitEvent(g_s2, g_ev1, 0);
        gemm_kernel<<<391, 256, 0, g_s2>>>(bufB, (half*)bufA, wh);    // M1 -> bufA (on s2)
        cudaEventRecord(g_ev2, g_s2);
    } else {
        gemm_kernel<<<391, 256>>>(bufB, (half*)bufA, wh);
    }

    deglb_kernel<<<(N_EDGES + 255) / 256, 256>>>(ei, bat);
    scan1_kernel<<<SCAN_NB, 256>>>();
    scan3_kernel<<<SCAN_NB, 256>>>();
    fill_kernel<<<(N_EDGES + 255) / 256, 256>>>(ei);

    if (fork) cudaStreamWaitEvent(0, g_ev2, 0);                       // join gemm1

    fused_kernel<<<TILES, 256>>>(bufA, (half*)bufB, wh + 1 * 2048, b1);   // M2 -> bufB
    fused_kernel<<<TILES, 256>>>(bufB, (half*)bufA, wh + 2 * 2048, b2);   // M3 -> bufA
    agg_kernel<<<NODE8, 256>>>(b3, bat, bufA);                            // pool

    final_kernel<<<(N_GRAPHS * N_CLASSES + 255) / 256, 256>>>(linW, linb, out);
}